// round 4
// baseline (speedup 1.0000x reference)
#include <cuda_runtime.h>
#include <math.h>

#define BS 4
#define NQ 6000
#define NV 13294
#define EMB 256
#define NH 8
#define HD 32

// Scratch (device globals: allocation-free per harness rules)
__device__ float g_v  [(size_t)BS * NV * EMB];   // value projection, [b*nv, h*32+c]
__device__ float g_off[(size_t)BS * NQ * 256];   // sampling offsets, [b*nq, h*32 + l*8 + p*2 + xy]
__device__ float g_aw [(size_t)BS * NQ * 128];   // attn logits,      [b*nq, h*16 + l*4 + p]
__device__ float g_mid[(size_t)BS * NQ * 256];   // aggregated heads, [b*nq, h*32 + c]

// ---------------------------------------------------------------------------
// Tiled fp32 GEMM: C[M,N] = A[M,K] @ B[K,N] + bias[N] (+ resid[M,N] if given)
// 128x128 tile, BK=16, 256 threads, 8x8 microtile via float4 fragments.
// Requires: N multiple of 128, K multiple of 16. M arbitrary (guarded).
// ---------------------------------------------------------------------------
__global__ __launch_bounds__(256, 2)
void sgemm128(const float* __restrict__ A, const float* __restrict__ B,
              const float* __restrict__ bias, const float* __restrict__ resid,
              float* __restrict__ C, int M, int N, int K)
{
    __shared__ float As[16][132];   // +4 pad: 2-way write conflicts, 16B-aligned rows
    __shared__ float Bs[16][128];

    const int tid = threadIdx.x;
    const int tx  = tid & 15;       // N direction
    const int ty  = tid >> 4;       // M direction
    const int row0 = blockIdx.y * 128;
    const int col0 = blockIdx.x * 128;

    float acc[8][8];
#pragma unroll
    for (int i = 0; i < 8; i++)
#pragma unroll
        for (int j = 0; j < 8; j++) acc[i][j] = 0.f;

    for (int k0 = 0; k0 < K; k0 += 16) {
        // Load A tile: As[k][m] = A[row0+m][k0+k]
#pragma unroll
        for (int i = tid; i < 128 * 16; i += 256) {
            int m = i >> 4, k = i & 15;
            int r = row0 + m;
            As[k][m] = (r < M) ? A[(size_t)r * K + k0 + k] : 0.f;
        }
        // Load B tile: Bs[k][n] = B[k0+k][col0+n]
#pragma unroll
        for (int i = tid; i < 16 * 128; i += 256) {
            int k = i >> 7, n = i & 127;
            Bs[k][n] = B[(size_t)(k0 + k) * N + col0 + n];
        }
        __syncthreads();

#pragma unroll
        for (int kk = 0; kk < 16; kk++) {
            float4 a0 = *(const float4*)&As[kk][ty * 4];
            float4 a1 = *(const float4*)&As[kk][64 + ty * 4];
            float4 b0 = *(const float4*)&Bs[kk][tx * 4];
            float4 b1 = *(const float4*)&Bs[kk][64 + tx * 4];
            float av[8] = {a0.x, a0.y, a0.z, a0.w, a1.x, a1.y, a1.z, a1.w};
            float bv[8] = {b0.x, b0.y, b0.z, b0.w, b1.x, b1.y, b1.z, b1.w};
#pragma unroll
            for (int i = 0; i < 8; i++)
#pragma unroll
                for (int j = 0; j < 8; j++)
                    acc[i][j] += av[i] * bv[j];
        }
        __syncthreads();
    }

    // Epilogue: bias + optional residual, float4 stores
#pragma unroll
    for (int ih = 0; ih < 2; ih++) {
#pragma unroll
        for (int ii = 0; ii < 4; ii++) {
            int r = row0 + ih * 64 + ty * 4 + ii;
            if (r >= M) continue;
#pragma unroll
            for (int jh = 0; jh < 2; jh++) {
                int c = col0 + jh * 64 + tx * 4;
                float4 o;
                o.x = acc[ih * 4 + ii][jh * 4 + 0] + bias[c + 0];
                o.y = acc[ih * 4 + ii][jh * 4 + 1] + bias[c + 1];
                o.z = acc[ih * 4 + ii][jh * 4 + 2] + bias[c + 2];
                o.w = acc[ih * 4 + ii][jh * 4 + 3] + bias[c + 3];
                if (resid) {
                    float4 rv = *(const float4*)&resid[(size_t)r * N + c];
                    o.x += rv.x; o.y += rv.y; o.z += rv.z; o.w += rv.w;
                }
                *(float4*)&C[(size_t)r * N + c] = o;
            }
        }
    }
}

// ---------------------------------------------------------------------------
// Deformable sampling: one warp per (b, q, h); lane = channel (coalesced 128B
// corner loads). Softmax + positions are lane-uniform (broadcast loads, no
// divergence).
// ---------------------------------------------------------------------------
__global__ __launch_bounds__(256)
void sample_kernel(const float* __restrict__ refp)
{
    const int LW[4]     = {100, 50, 25, 13};
    const int LH[4]     = {100, 50, 25, 13};
    const int LSTART[4] = {0, 10000, 12500, 13125};

    int gt   = blockIdx.x * blockDim.x + threadIdx.x;
    int warp = gt >> 5;
    int lane = gt & 31;
    if (warp >= BS * NQ * NH) return;

    int h  = warp & 7;
    int bq = warp >> 3;     // b*NQ + q
    int b  = bq / NQ;

    // Softmax over the 16 (level, point) logits for this head
    const float* awp = g_aw + (size_t)bq * 128 + h * 16;
    float lg[16];
    float mx = -1e30f;
#pragma unroll
    for (int i = 0; i < 16; i++) { lg[i] = awp[i]; mx = fmaxf(mx, lg[i]); }
    float s = 0.f;
#pragma unroll
    for (int i = 0; i < 16; i++) { lg[i] = __expf(lg[i] - mx); s += lg[i]; }
    const float inv = 1.0f / s;

    const float* offp = g_off + (size_t)bq * 256 + h * 32;
    const float* rp   = refp + (size_t)bq * 8;

    float acc = 0.f;
#pragma unroll
    for (int l = 0; l < 4; l++) {
        const float rx = rp[l * 2 + 0];
        const float ry = rp[l * 2 + 1];
        const int   W = LW[l], H = LH[l];
        const float* vb = g_v + ((size_t)(b * NV + LSTART[l])) * EMB + h * HD + lane;
#pragma unroll
        for (int p = 0; p < 4; p++) {
            // pixel coords: x = loc_x*W - 0.5 = rx*W + off_x - 0.5 (align_corners=False)
            float x = rx * (float)W + offp[l * 8 + p * 2 + 0] - 0.5f;
            float y = ry * (float)H + offp[l * 8 + p * 2 + 1] - 0.5f;
            float xf = floorf(x), yf = floorf(y);
            int   x0 = (int)xf,  y0 = (int)yf;
            float wx1 = x - xf, wy1 = y - yf;
            float wx0 = 1.f - wx1, wy0 = 1.f - wy1;
            float wp = lg[l * 4 + p] * inv;

            bool vx0 = (x0 >= 0)     && (x0 < W);
            bool vx1 = (x0 + 1 >= 0) && (x0 + 1 < W);
            bool vy0 = (y0 >= 0)     && (y0 < H);
            bool vy1 = (y0 + 1 >= 0) && (y0 + 1 < H);

            float sval = 0.f;
            if (vy0) {
                const float* r0 = vb + (ptrdiff_t)y0 * W * EMB;
                if (vx0) sval += wx0 * wy0 * r0[(ptrdiff_t)x0 * EMB];
                if (vx1) sval += wx1 * wy0 * r0[(ptrdiff_t)(x0 + 1) * EMB];
            }
            if (vy1) {
                const float* r1 = vb + (ptrdiff_t)(y0 + 1) * W * EMB;
                if (vx0) sval += wx0 * wy1 * r1[(ptrdiff_t)x0 * EMB];
                if (vx1) sval += wx1 * wy1 * r1[(ptrdiff_t)(x0 + 1) * EMB];
            }
            acc += wp * sval;
        }
    }
    g_mid[(size_t)bq * 256 + h * HD + lane] = acc;
}

// ---------------------------------------------------------------------------
extern "C" void kernel_launch(void* const* d_in, const int* in_sizes, int n_in,
                              void* d_out, int out_size)
{
    const float* query  = (const float*)d_in[0];
    const float* value  = (const float*)d_in[1];
    const float* refp   = (const float*)d_in[2];
    const float* W_off  = (const float*)d_in[3];
    const float* b_off  = (const float*)d_in[4];
    const float* W_attn = (const float*)d_in[5];
    const float* b_attn = (const float*)d_in[6];
    const float* W_val  = (const float*)d_in[7];
    const float* b_val  = (const float*)d_in[8];
    const float* W_out  = (const float*)d_in[9];
    const float* b_out  = (const float*)d_in[10];
    // d_in[11] = spatial_shapes (constants hardcoded)
    float* out = (float*)d_out;

    float *pv, *poff, *paw, *pmid;
    cudaGetSymbolAddress((void**)&pv,   g_v);
    cudaGetSymbolAddress((void**)&poff, g_off);
    cudaGetSymbolAddress((void**)&paw,  g_aw);
    cudaGetSymbolAddress((void**)&pmid, g_mid);

    const dim3 blk(256);

    // 1) value projection: [BS*NV,256] @ [256,256] + b_val
    sgemm128<<<dim3(2, (BS * NV + 127) / 128), blk>>>(
        value, W_val, b_val, nullptr, pv, BS * NV, 256, 256);

    // 2) sampling-offset projection: [BS*NQ,256] @ [256,256] + b_off
    sgemm128<<<dim3(2, (BS * NQ + 127) / 128), blk>>>(
        query, W_off, b_off, nullptr, poff, BS * NQ, 256, 256);

    // 3) attention-weight projection: [BS*NQ,256] @ [256,128] + b_attn
    sgemm128<<<dim3(1, (BS * NQ + 127) / 128), blk>>>(
        query, W_attn, b_attn, nullptr, paw, BS * NQ, 128, 256);

    // 4) softmax + bilinear sampling + weighted aggregation
    sample_kernel<<<(BS * NQ * NH * 32 + 255) / 256, 256>>>(refp);

    // 5) output projection + residual: g_mid @ W_out + b_out + query
    sgemm128<<<dim3(2, (BS * NQ + 127) / 128), blk>>>(
        pmid, W_out, b_out, query, out, BS * NQ, 256, 256);
}

// round 5
// speedup vs baseline: 1.2076x; 1.2076x over previous
#include <cuda_runtime.h>
#include <mma.h>
#include <math.h>

using namespace nvcuda;

#define BS 4
#define NQ 6000
#define NV 13294
#define EMB 256
#define NH 8
#define HD 32

#define MV (BS * NV)          // 53176
#define MQ (BS * NQ)          // 24000
#define MV_PAD 53248          // 416 * 128
#define MQ_PAD 24064          // 188 * 128

// Scratch (device globals: allocation-free per harness rules). Padded to
// 128-row multiples so tf32 GEMM tiles never write out of bounds.
__device__ float g_v  [(size_t)MV_PAD * EMB];   // value projection, [b*nv, h*32+c]
__device__ float g_off[(size_t)MQ_PAD * 256];   // sampling offsets
__device__ float g_aw [(size_t)MQ_PAD * 128];   // attn logits
__device__ float g_mid[(size_t)MQ_PAD * 256];   // aggregated heads

// ---------------------------------------------------------------------------
// C initializer: C[r][c] = bias[c] (+ resid[r][c]). GEMM accumulators are
// loaded from C, so bias + residual come for free in the MMA epilogue.
// ---------------------------------------------------------------------------
__global__ void init_c(const float* __restrict__ bias, const float* __restrict__ resid,
                       float* __restrict__ C, int M, int N)
{
    int i = blockIdx.x * blockDim.x + threadIdx.x;   // float4 index
    int nv4 = N >> 2;
    if (i >= M * nv4) return;
    int r = i / nv4, c4 = i - r * nv4;
    float4 o = ((const float4*)bias)[c4];
    if (resid) {
        float4 rv = ((const float4*)resid)[(size_t)r * nv4 + c4];
        o.x += rv.x; o.y += rv.y; o.z += rv.z; o.w += rv.w;
    }
    ((float4*)C)[(size_t)r * nv4 + c4] = o;
}

// ---------------------------------------------------------------------------
// TF32 tensor-core GEMM: C += A @ B  (C pre-initialized with bias/resid).
// 128x128 block tile, BK=32, 256 threads = 8 warps (4x2), warp tile 32x64,
// wmma 16x16x8 tf32 with fp32 accumulate.
//   M      : rows of A actually readable (A loads zero-guarded beyond)
//   Mstore : rows of C writable; warp skips load+store if its 32-row span
//            starts >= Mstore (requires Mstore % 32 == 0 or padded C).
// ---------------------------------------------------------------------------
#define LDA_S 40    // 128 x 32 A tile, padded row stride (16B-aligned rows)
#define LDB_S 136   // 32 x 128 B tile, padded row stride

__global__ __launch_bounds__(256, 2)
void gemm_tf32(const float* __restrict__ A, const float* __restrict__ B,
               float* __restrict__ C, int M, int N, int K, int Mstore)
{
    __shared__ float As[128 * LDA_S];
    __shared__ float Bs[32 * LDB_S];

    const int tid = threadIdx.x;
    const int wid = tid >> 5;
    const int warp_m = wid >> 1;     // 0..3
    const int warp_n = wid & 1;      // 0..1
    const int row0 = blockIdx.y * 128;
    const int col0 = blockIdx.x * 128;

    const bool wvalid = (row0 + warp_m * 32) < Mstore;

    wmma::fragment<wmma::accumulator, 16, 16, 8, float> acc[2][4];

    // Initialize accumulators from pre-written C (bias + optional residual)
#pragma unroll
    for (int i = 0; i < 2; i++)
#pragma unroll
        for (int j = 0; j < 4; j++) {
            if (wvalid)
                wmma::load_matrix_sync(acc[i][j],
                    C + (size_t)(row0 + warp_m * 32 + i * 16) * N + col0 + warp_n * 64 + j * 16,
                    N, wmma::mem_row_major);
            else
                wmma::fill_fragment(acc[i][j], 0.0f);
        }

    const int ar  = tid >> 3;        // A tile row 0..31 (x4 iters)
    const int ac4 = tid & 7;         // A float4 column

    for (int k0 = 0; k0 < K; k0 += 32) {
        // Load A tile 128x32 (row-major, zero-guarded rows)
#pragma unroll
        for (int it = 0; it < 4; it++) {
            int m = ar + it * 32;
            int r = row0 + m;
            float4 v = make_float4(0.f, 0.f, 0.f, 0.f);
            if (r < M) v = ((const float4*)(A + (size_t)r * K + k0))[ac4];
            *(float4*)&As[m * LDA_S + ac4 * 4] = v;
        }
        // Load B tile 32x128 (row-major)
#pragma unroll
        for (int it = 0; it < 4; it++) {
            int idx = tid + it * 256;        // float4 index within 32x32f4
            int k = idx >> 5, n4 = idx & 31;
            float4 v = ((const float4*)(B + (size_t)(k0 + k) * N + col0))[n4];
            *(float4*)&Bs[k * LDB_S + n4 * 4] = v;
        }
        __syncthreads();

#pragma unroll
        for (int kk = 0; kk < 4; kk++) {
            wmma::fragment<wmma::matrix_a, 16, 16, 8, wmma::precision::tf32, wmma::row_major> a[2];
            wmma::fragment<wmma::matrix_b, 16, 16, 8, wmma::precision::tf32, wmma::row_major> b[4];
#pragma unroll
            for (int i = 0; i < 2; i++) {
                wmma::load_matrix_sync(a[i], &As[(warp_m * 32 + i * 16) * LDA_S + kk * 8], LDA_S);
#pragma unroll
                for (int t = 0; t < a[i].num_elements; t++)
                    a[i].x[t] = wmma::__float_to_tf32(a[i].x[t]);
            }
#pragma unroll
            for (int j = 0; j < 4; j++) {
                wmma::load_matrix_sync(b[j], &Bs[(kk * 8) * LDB_S + warp_n * 64 + j * 16], LDB_S);
#pragma unroll
                for (int t = 0; t < b[j].num_elements; t++)
                    b[j].x[t] = wmma::__float_to_tf32(b[j].x[t]);
            }
#pragma unroll
            for (int i = 0; i < 2; i++)
#pragma unroll
                for (int j = 0; j < 4; j++)
                    wmma::mma_sync(acc[i][j], a[i], b[j], acc[i][j]);
        }
        __syncthreads();
    }

    if (wvalid) {
#pragma unroll
        for (int i = 0; i < 2; i++)
#pragma unroll
            for (int j = 0; j < 4; j++)
                wmma::store_matrix_sync(
                    C + (size_t)(row0 + warp_m * 32 + i * 16) * N + col0 + warp_n * 64 + j * 16,
                    acc[i][j], N, wmma::mem_row_major);
    }
}

// ---------------------------------------------------------------------------
// Deformable sampling: one warp per (b, q, h); lane = channel (coalesced 128B
// corner loads). Branch-free: corner indices clamped in-bounds, validity
// folded into bilinear weights; all index math in 32-bit.
// ---------------------------------------------------------------------------
__global__ __launch_bounds__(256)
void sample_kernel(const float* __restrict__ refp)
{
    int gt   = blockIdx.x * blockDim.x + threadIdx.x;
    int warp = gt >> 5;
    int lane = gt & 31;
    if (warp >= MQ * NH) return;

    int h  = warp & 7;
    int bq = warp >> 3;
    int b  = bq / NQ;

    // Softmax numerator over 16 (level, point) logits; 1/sum folded at end
    const float* awp = g_aw + bq * 128 + h * 16;
    float lg[16];
    float mx = -1e30f;
#pragma unroll
    for (int i = 0; i < 16; i++) { lg[i] = awp[i]; mx = fmaxf(mx, lg[i]); }
    float s = 0.f;
#pragma unroll
    for (int i = 0; i < 16; i++) { lg[i] = __expf(lg[i] - mx); s += lg[i]; }
    const float inv = 1.0f / s;

    const float* offp = g_off + bq * 256 + h * 32;
    const float* rp   = refp + bq * 8;

    const int vbase0 = ((b * NV) << 8) + h * HD + lane;   // fits in int32

    float acc = 0.f;
#pragma unroll
    for (int l = 0; l < 4; l++) {
        const int W     = (l == 0 ? 100 : l == 1 ? 50 : l == 2 ? 25 : 13);
        const int START = (l == 0 ? 0 : l == 1 ? 10000 : l == 2 ? 12500 : 13125);
        const int RSTR  = W << 8;                         // row stride (floats)
        const float* vb = g_v + vbase0 + (START << 8);
        const float rx = rp[l * 2 + 0];
        const float ry = rp[l * 2 + 1];
#pragma unroll
        for (int p = 0; p < 4; p++) {
            float x = fmaf(rx, (float)W, offp[l * 8 + p * 2 + 0]) - 0.5f;
            float y = fmaf(ry, (float)W, offp[l * 8 + p * 2 + 1]) - 0.5f;
            float xf = floorf(x), yf = floorf(y);
            int   x0 = (int)xf,  y0 = (int)yf;
            float wx1 = x - xf, wy1 = y - yf;
            float wx0 = 1.f - wx1, wy0 = 1.f - wy1;

            // Fold OOB validity into the weights (padding_mode='zeros')
            wx0 *= (float)(x0 >= 0 && x0 < W);
            wx1 *= (float)(x0 >= -1 && x0 < W - 1);
            wy0 *= (float)(y0 >= 0 && y0 < W);
            wy1 *= (float)(y0 >= -1 && y0 < W - 1);

            int xc0 = min(max(x0, 0), W - 1);
            int xc1 = min(max(x0 + 1, 0), W - 1);
            int yc0 = min(max(y0, 0), W - 1);
            int yc1 = min(max(y0 + 1, 0), W - 1);

            const float* r0 = vb + yc0 * RSTR;
            const float* r1 = vb + yc1 * RSTR;
            float v00 = r0[xc0 << 8];
            float v01 = r0[xc1 << 8];
            float v10 = r1[xc0 << 8];
            float v11 = r1[xc1 << 8];

            float c0 = fmaf(wy1, v10, wy0 * v00);
            float c1 = fmaf(wy1, v11, wy0 * v01);
            float sval = fmaf(wx1, c1, wx0 * c0);
            acc = fmaf(lg[l * 4 + p], sval, acc);
        }
    }
    g_mid[bq * 256 + h * HD + lane] = acc * inv;
}

// ---------------------------------------------------------------------------
extern "C" void kernel_launch(void* const* d_in, const int* in_sizes, int n_in,
                              void* d_out, int out_size)
{
    const float* query  = (const float*)d_in[0];
    const float* value  = (const float*)d_in[1];
    const float* refp   = (const float*)d_in[2];
    const float* W_off  = (const float*)d_in[3];
    const float* b_off  = (const float*)d_in[4];
    const float* W_attn = (const float*)d_in[5];
    const float* b_attn = (const float*)d_in[6];
    const float* W_val  = (const float*)d_in[7];
    const float* b_val  = (const float*)d_in[8];
    const float* W_out  = (const float*)d_in[9];
    const float* b_out  = (const float*)d_in[10];
    float* out = (float*)d_out;

    float *pv, *poff, *paw, *pmid;
    cudaGetSymbolAddress((void**)&pv,   g_v);
    cudaGetSymbolAddress((void**)&poff, g_off);
    cudaGetSymbolAddress((void**)&paw,  g_aw);
    cudaGetSymbolAddress((void**)&pmid, g_mid);

    // 1) value projection: g_v = value @ W_val + b_val
    init_c<<<(MV_PAD * 64 + 255) / 256, 256>>>(b_val, nullptr, pv, MV_PAD, 256);
    gemm_tf32<<<dim3(2, MV_PAD / 128), 256>>>(value, W_val, pv, MV, 256, 256, MV_PAD);

    // 2) sampling-offset projection: g_off = query @ W_off + b_off
    init_c<<<(MQ_PAD * 64 + 255) / 256, 256>>>(b_off, nullptr, poff, MQ_PAD, 256);
    gemm_tf32<<<dim3(2, MQ_PAD / 128), 256>>>(query, W_off, poff, MQ, 256, 256, MQ_PAD);

    // 3) attention-weight projection: g_aw = query @ W_attn + b_attn
    init_c<<<(MQ_PAD * 32 + 255) / 256, 256>>>(b_attn, nullptr, paw, MQ_PAD, 128);
    gemm_tf32<<<dim3(1, MQ_PAD / 128), 256>>>(query, W_attn, paw, MQ, 128, 256, MQ_PAD);

    // 4) softmax + bilinear sampling + weighted aggregation
    sample_kernel<<<(MQ * NH * 32 + 255) / 256, 256>>>(refp);

    // 5) output projection + residual: out = g_mid @ W_out + b_out + query
    init_c<<<(MQ * 64 + 255) / 256, 256>>>(b_out, query, out, MQ, 256);
    gemm_tf32<<<dim3(2, MQ_PAD / 128), 256>>>(pmid, W_out, out, MQ, 256, 256, MQ);
}

// round 6
// speedup vs baseline: 1.5325x; 1.2690x over previous
#include <cuda_runtime.h>
#include <cuda_bf16.h>
#include <mma.h>
#include <math.h>
#include <stdint.h>

using namespace nvcuda;

#define BS 4
#define NQ 6000
#define NV 13294
#define EMB 256
#define NH 8
#define HD 32

#define MV (BS * NV)          // 53176
#define MQ (BS * NQ)          // 24000
#define MV_PAD 53248          // 416 * 128
#define MQ_PAD 24064          // 188 * 128

// Scratch (device globals: allocation-free per harness rules).
__device__ float         g_v   [(size_t)MV_PAD * EMB];     // value proj fp32
__device__ __nv_bfloat16 g_vb  [(size_t)MV_PAD * EMB];     // value proj bf16 (gather source)
__device__ float         g_off [(size_t)MQ_PAD * 256];     // sampling offsets
__device__ float         g_aw  [(size_t)MQ_PAD * 128];     // attn logits
__device__ float         g_mid [(size_t)MQ_PAD * 256];     // aggregated heads
__device__ float         g_samp[(size_t)MQ * NH * 128];    // per-point {int4 idx, float4 w}
__device__ float         g_brep[4 * 16 * 256];             // 16-row-replicated bias tiles

// ---------------------------------------------------------------------------
// Fill the 4 replicated bias tiles (16 identical rows each) used to seed the
// GEMM accumulators via load_matrix_sync.
// tile 0: b_val, 1: b_off, 2: b_attn (N=128), 3: b_out
// ---------------------------------------------------------------------------
__global__ void fill_brep(const float* __restrict__ b0, const float* __restrict__ b1,
                          const float* __restrict__ b2, const float* __restrict__ b3)
{
    int i = blockIdx.x * blockDim.x + threadIdx.x;
    if (i >= 4 * 16 * 256) return;
    int t = i >> 12;            // tile
    int c = i & 255;            // column
    const float* b = (t == 0) ? b0 : (t == 1) ? b1 : (t == 2) ? b2 : b3;
    g_brep[i] = (t == 2) ? b[c & 127] : b[c];
}

// ---------------------------------------------------------------------------
// TF32 tensor-core GEMM, cp.async double-buffered.
// C = A @ B + bias (via brep accumulator seed) [+ resid fragment in epilogue]
// 128x128 block tile, BK=32, 256 threads = 8 warps (4x2), warp tile 32x64.
//   M      : readable rows of A (cp.async zero-fills beyond)
//   Mstore : writable rows of C at warp (32-row) granularity
// ---------------------------------------------------------------------------
#define AS_STRIDE 40
#define BS_STRIDE 136
#define AS_STAGE (128 * AS_STRIDE)      // floats per A stage
#define BS_STAGE (32 * BS_STRIDE)       // floats per B stage
#define GEMM_SMEM ((2 * AS_STAGE + 2 * BS_STAGE) * 4)   // 75776 bytes

__device__ __forceinline__ void cp16(float* dst_smem, const float* src, int src_bytes)
{
    uint32_t d = (uint32_t)__cvta_generic_to_shared(dst_smem);
    asm volatile("cp.async.cg.shared.global [%0], [%1], 16, %2;\n"
                 :: "r"(d), "l"(src), "r"(src_bytes));
}

__global__ __launch_bounds__(256, 2)
void gemm_tf32(const float* __restrict__ A, const float* __restrict__ B,
               const float* __restrict__ brep, const float* __restrict__ resid,
               float* __restrict__ C, int M, int N, int K, int Mstore)
{
    extern __shared__ float sm[];
    float* As = sm;
    float* Bsm = sm + 2 * AS_STAGE;

    const int tid = threadIdx.x;
    const int wid = tid >> 5;
    const int warp_m = wid >> 1;     // 0..3
    const int warp_n = wid & 1;      // 0..1
    const int row0 = blockIdx.y * 128;
    const int col0 = blockIdx.x * 128;
    const bool wvalid = (row0 + warp_m * 32) < Mstore;

    // Accumulators seeded with bias (16-row replicated tile, ldm=256)
    wmma::fragment<wmma::accumulator, 16, 16, 8, float> acc[2][4];
#pragma unroll
    for (int i = 0; i < 2; i++)
#pragma unroll
        for (int j = 0; j < 4; j++)
            wmma::load_matrix_sync(acc[i][j],
                brep + col0 + warp_n * 64 + j * 16, 256, wmma::mem_row_major);

    const int am  = tid >> 3;        // A tile row (x4 iters of 32)
    const int af4 = tid & 7;         // A float4 column
    const int bk  = tid >> 5;        // B tile row base (x4 iters of 8)
    const int bn4 = tid & 31;        // B float4 column

    const int iters = K >> 5;

    // stage prefetch
    auto prefetch = [&](int k0, int st) {
#pragma unroll
        for (int it = 0; it < 4; it++) {
            int m = am + it * 32;
            int r = row0 + m;
            cp16(&As[st * AS_STAGE + m * AS_STRIDE + af4 * 4],
                 A + (size_t)r * K + k0 + af4 * 4, (r < M) ? 16 : 0);
        }
#pragma unroll
        for (int it = 0; it < 4; it++) {
            int k = bk + it * 8;
            cp16(&Bsm[st * BS_STAGE + k * BS_STRIDE + bn4 * 4],
                 B + (size_t)(k0 + k) * N + col0 + bn4 * 4, 16);
        }
        asm volatile("cp.async.commit_group;\n");
    };

    prefetch(0, 0);

    for (int i = 0; i < iters; i++) {
        if (i + 1 < iters) {
            prefetch((i + 1) << 5, (i + 1) & 1);
            asm volatile("cp.async.wait_group 1;\n");
        } else {
            asm volatile("cp.async.wait_group 0;\n");
        }
        __syncthreads();

        const float* as = As + (i & 1) * AS_STAGE;
        const float* bs = Bsm + (i & 1) * BS_STAGE;

#pragma unroll
        for (int kk = 0; kk < 4; kk++) {
            wmma::fragment<wmma::matrix_a, 16, 16, 8, wmma::precision::tf32, wmma::row_major> a[2];
            wmma::fragment<wmma::matrix_b, 16, 16, 8, wmma::precision::tf32, wmma::row_major> b[4];
#pragma unroll
            for (int ii = 0; ii < 2; ii++) {
                wmma::load_matrix_sync(a[ii], as + (warp_m * 32 + ii * 16) * AS_STRIDE + kk * 8, AS_STRIDE);
#pragma unroll
                for (int t = 0; t < a[ii].num_elements; t++)
                    a[ii].x[t] = wmma::__float_to_tf32(a[ii].x[t]);
            }
#pragma unroll
            for (int j = 0; j < 4; j++) {
                wmma::load_matrix_sync(b[j], bs + (kk * 8) * BS_STRIDE + warp_n * 64 + j * 16, BS_STRIDE);
#pragma unroll
                for (int t = 0; t < b[j].num_elements; t++)
                    b[j].x[t] = wmma::__float_to_tf32(b[j].x[t]);
            }
#pragma unroll
            for (int ii = 0; ii < 2; ii++)
#pragma unroll
                for (int j = 0; j < 4; j++)
                    wmma::mma_sync(acc[ii][j], a[ii], b[j], acc[ii][j]);
        }
        __syncthreads();
    }

    if (wvalid) {
#pragma unroll
        for (int i = 0; i < 2; i++)
#pragma unroll
            for (int j = 0; j < 4; j++) {
                float* cp = C + (size_t)(row0 + warp_m * 32 + i * 16) * N + col0 + warp_n * 64 + j * 16;
                if (resid) {
                    wmma::fragment<wmma::accumulator, 16, 16, 8, float> r;
                    wmma::load_matrix_sync(r,
                        resid + (size_t)(row0 + warp_m * 32 + i * 16) * N + col0 + warp_n * 64 + j * 16,
                        N, wmma::mem_row_major);
#pragma unroll
                    for (int t = 0; t < r.num_elements; t++)
                        acc[i][j].x[t] += r.x[t];
                }
                wmma::store_matrix_sync(cp, acc[i][j], N, wmma::mem_row_major);
            }
    }
}

// ---------------------------------------------------------------------------
// fp32 -> bf16 conversion of the value cache (float4 in, 2x bf162 out)
// ---------------------------------------------------------------------------
__global__ void cvt_bf16(int n4)
{
    int i = blockIdx.x * blockDim.x + threadIdx.x;
    if (i >= n4) return;
    float4 v = ((const float4*)g_v)[i];
    __nv_bfloat162* o = (__nv_bfloat162*)g_vb;
    o[2 * i]     = __floats2bfloat162_rn(v.x, v.y);
    o[2 * i + 1] = __floats2bfloat162_rn(v.z, v.w);
}

// ---------------------------------------------------------------------------
// Precompute: one thread per (b,q,h). Softmax + positions + clamped corner
// indices + validity-masked combined weights, written once so the gather warp
// does no redundant per-lane ALU.
// Layout per (b,q,h): 16 points x {int4 corner-elem-idx, float4 weights} = 128 floats.
// ---------------------------------------------------------------------------
__global__ __launch_bounds__(256)
void precompute(const float* __restrict__ refp)
{
    int t = blockIdx.x * blockDim.x + threadIdx.x;
    if (t >= MQ * NH) return;
    int h  = t & 7;
    int bq = t >> 3;
    int b  = bq / NQ;

    const float* awp = g_aw + bq * 128 + h * 16;
    float lg[16];
    float mx = -1e30f;
#pragma unroll
    for (int i = 0; i < 16; i++) { lg[i] = awp[i]; mx = fmaxf(mx, lg[i]); }
    float s = 0.f;
#pragma unroll
    for (int i = 0; i < 16; i++) { lg[i] = __expf(lg[i] - mx); s += lg[i]; }
    const float inv = 1.0f / s;

    const float* offp = g_off + bq * 256 + h * 32;
    const float* rp   = refp + bq * 8;
    float* op = g_samp + (size_t)t * 128;
    const int rowbase = b * NV;
    const int hh = h * HD;

#pragma unroll
    for (int l = 0; l < 4; l++) {
        const int W     = (l == 0 ? 100 : l == 1 ? 50 : l == 2 ? 25 : 13);
        const int START = (l == 0 ? 0 : l == 1 ? 10000 : l == 2 ? 12500 : 13125);
        const int base  = rowbase + START;
        const float rx = rp[l * 2 + 0];
        const float ry = rp[l * 2 + 1];
#pragma unroll
        for (int p = 0; p < 4; p++) {
            float x = fmaf(rx, (float)W, offp[l * 8 + p * 2 + 0]) - 0.5f;
            float y = fmaf(ry, (float)W, offp[l * 8 + p * 2 + 1]) - 0.5f;
            float xf = floorf(x), yf = floorf(y);
            int   x0 = (int)xf,  y0 = (int)yf;
            float wx1 = x - xf, wy1 = y - yf;
            float wx0 = 1.f - wx1, wy0 = 1.f - wy1;

            // padding_mode='zeros': fold OOB validity into the weights
            wx0 *= (float)(x0 >= 0 && x0 < W);
            wx1 *= (float)(x0 >= -1 && x0 < W - 1);
            wy0 *= (float)(y0 >= 0 && y0 < W);
            wy1 *= (float)(y0 >= -1 && y0 < W - 1);

            int xc0 = min(max(x0, 0), W - 1);
            int xc1 = min(max(x0 + 1, 0), W - 1);
            int yc0 = min(max(y0, 0), W - 1);
            int yc1 = min(max(y0 + 1, 0), W - 1);

            float wp = lg[l * 4 + p] * inv;
            int r0 = (base + yc0 * W) << 8;
            int r1 = (base + yc1 * W) << 8;

            int4 ii;
            ii.x = r0 + (xc0 << 8) + hh;
            ii.y = r0 + (xc1 << 8) + hh;
            ii.z = r1 + (xc0 << 8) + hh;
            ii.w = r1 + (xc1 << 8) + hh;
            *(int4*)(op + (l * 4 + p) * 8)       = ii;
            *(float4*)(op + (l * 4 + p) * 8 + 4) =
                make_float4(wp * wy0 * wx0, wp * wy0 * wx1, wp * wy1 * wx0, wp * wy1 * wx1);
        }
    }
}

// ---------------------------------------------------------------------------
// Gather: one warp per (b,q,h); lane = channel. Lean loop: 2 uniform 16B
// metadata loads + 4 coalesced 64B bf16 corner loads + 4 FMA per point.
// ---------------------------------------------------------------------------
__global__ __launch_bounds__(256)
void gather_kernel()
{
    int gt   = blockIdx.x * blockDim.x + threadIdx.x;
    int warp = gt >> 5;
    int lane = gt & 31;
    if (warp >= MQ * NH) return;

    const float* md = g_samp + (size_t)warp * 128;
    const __nv_bfloat16* vb = g_vb;

    float acc = 0.f;
#pragma unroll
    for (int pt = 0; pt < 16; pt++) {
        int4   ii = *(const int4*)(md + pt * 8);
        float4 ww = *(const float4*)(md + pt * 8 + 4);
        float v00 = __bfloat162float(vb[ii.x + lane]);
        float v01 = __bfloat162float(vb[ii.y + lane]);
        float v10 = __bfloat162float(vb[ii.z + lane]);
        float v11 = __bfloat162float(vb[ii.w + lane]);
        acc = fmaf(ww.x, v00, acc);
        acc = fmaf(ww.y, v01, acc);
        acc = fmaf(ww.z, v10, acc);
        acc = fmaf(ww.w, v11, acc);
    }

    int h  = warp & 7;
    int bq = warp >> 3;
    g_mid[bq * 256 + h * HD + lane] = acc;
}

// ---------------------------------------------------------------------------
extern "C" void kernel_launch(void* const* d_in, const int* in_sizes, int n_in,
                              void* d_out, int out_size)
{
    const float* query  = (const float*)d_in[0];
    const float* value  = (const float*)d_in[1];
    const float* refp   = (const float*)d_in[2];
    const float* W_off  = (const float*)d_in[3];
    const float* b_off  = (const float*)d_in[4];
    const float* W_attn = (const float*)d_in[5];
    const float* b_attn = (const float*)d_in[6];
    const float* W_val  = (const float*)d_in[7];
    const float* b_val  = (const float*)d_in[8];
    const float* W_out  = (const float*)d_in[9];
    const float* b_out  = (const float*)d_in[10];
    float* out = (float*)d_out;

    float *pv, *poff, *paw, *pmid, *pbrep;
    cudaGetSymbolAddress((void**)&pv,    g_v);
    cudaGetSymbolAddress((void**)&poff,  g_off);
    cudaGetSymbolAddress((void**)&paw,   g_aw);
    cudaGetSymbolAddress((void**)&pmid,  g_mid);
    cudaGetSymbolAddress((void**)&pbrep, g_brep);

    cudaFuncSetAttribute(gemm_tf32, cudaFuncAttributeMaxDynamicSharedMemorySize, GEMM_SMEM);

    // 0) replicated bias tiles
    fill_brep<<<64, 256>>>(b_val, b_off, b_attn, b_out);

    // 1) value projection (fp32) then bf16 cache
    gemm_tf32<<<dim3(2, MV_PAD / 128), 256, GEMM_SMEM>>>(
        value, W_val, pbrep + 0 * 4096, nullptr, pv, MV, 256, 256, MV_PAD);
    cvt_bf16<<<(MV * 64 + 255) / 256, 256>>>(MV * 64);

    // 2) sampling-offset projection
    gemm_tf32<<<dim3(2, MQ_PAD / 128), 256, GEMM_SMEM>>>(
        query, W_off, pbrep + 1 * 4096, nullptr, poff, MQ, 256, 256, MQ_PAD);

    // 3) attention-weight projection (N=128)
    gemm_tf32<<<dim3(1, MQ_PAD / 128), 256, GEMM_SMEM>>>(
        query, W_attn, pbrep + 2 * 4096, nullptr, paw, MQ, 128, 256, MQ_PAD);

    // 4) per-(b,q,h) softmax + position precompute, then warp gather
    precompute<<<(MQ * NH + 255) / 256, 256>>>(refp);
    gather_kernel<<<(MQ * NH * 32 + 255) / 256, 256>>>();

    // 5) output projection + bias + fp32 residual
    gemm_tf32<<<dim3(2, MQ_PAD / 128), 256, GEMM_SMEM>>>(
        pmid, W_out, pbrep + 3 * 4096, query, out, MQ, 256, 256, MQ);
}

// round 7
// speedup vs baseline: 1.9418x; 1.2671x over previous
#include <cuda_runtime.h>
#include <cuda_bf16.h>
#include <mma.h>
#include <math.h>
#include <stdint.h>

using namespace nvcuda;

#define BS 4
#define NQ 6000
#define NV 13294
#define EMB 256
#define NH 8
#define HD 32

#define MV (BS * NV)          // 53176
#define MQ (BS * NQ)          // 24000
#define MV_PAD 53248          // 416 * 128
#define MQ_PAD 24064          // 188 * 128

// Scratch (device globals: allocation-free per harness rules).
__device__ __nv_bfloat16 g_vb [(size_t)MV_PAD * EMB];   // value proj bf16 (gather source)
__device__ float         g_off[(size_t)MQ_PAD * 256];   // sampling offsets
__device__ float         g_aw [(size_t)MQ_PAD * 128];   // attn logits
__device__ float         g_mid[(size_t)MQ_PAD * 256];   // aggregated heads
__device__ float         g_brep[4 * 16 * 256];          // 16-row-replicated bias tiles

// ---------------------------------------------------------------------------
// Fill the 4 replicated bias tiles (16 identical rows each) used to seed the
// GEMM accumulators via load_matrix_sync.
// tile 0: b_val, 1: b_off, 2: b_attn (N=128), 3: b_out
// ---------------------------------------------------------------------------
__global__ void fill_brep(const float* __restrict__ b0, const float* __restrict__ b1,
                          const float* __restrict__ b2, const float* __restrict__ b3)
{
    int i = blockIdx.x * blockDim.x + threadIdx.x;
    if (i >= 4 * 16 * 256) return;
    int t = i >> 12;
    int c = i & 255;
    const float* b = (t == 0) ? b0 : (t == 1) ? b1 : (t == 2) ? b2 : b3;
    g_brep[i] = (t == 2) ? b[c & 127] : b[c];
}

// ---------------------------------------------------------------------------
// TF32 tensor-core GEMM, cp.async double-buffered, no explicit f32->tf32
// conversion (HW reads only the tf32 bits; RZ truncation).
// C = A @ B + bias (brep accumulator seed) [+ resid fragment in epilogue]
// OUTBF16: epilogue converts to bf16 and writes Cb instead (for value proj).
// 128x128 block tile, BK=32, 256 threads = 8 warps (4x2), warp tile 32x64.
// ---------------------------------------------------------------------------
#define AS_STRIDE 40
#define BS_STRIDE 136
#define AS_STAGE (128 * AS_STRIDE)
#define BS_STAGE (32 * BS_STRIDE)
#define GEMM_SMEM ((2 * AS_STAGE + 2 * BS_STAGE) * 4)   // 75776 bytes

__device__ __forceinline__ void cp16(float* dst_smem, const float* src, int src_bytes)
{
    uint32_t d = (uint32_t)__cvta_generic_to_shared(dst_smem);
    asm volatile("cp.async.cg.shared.global [%0], [%1], 16, %2;\n"
                 :: "r"(d), "l"(src), "r"(src_bytes));
}

template <int OUTBF16>
__global__ __launch_bounds__(256, 2)
void gemm_tf32(const float* __restrict__ A, const float* __restrict__ B,
               const float* __restrict__ brep, const float* __restrict__ resid,
               float* __restrict__ C, __nv_bfloat16* __restrict__ Cb,
               int M, int N, int K, int Mstore)
{
    extern __shared__ float sm[];
    float* As = sm;
    float* Bsm = sm + 2 * AS_STAGE;

    const int tid = threadIdx.x;
    const int lane = tid & 31;
    const int wid = tid >> 5;
    const int warp_m = wid >> 1;
    const int warp_n = wid & 1;
    const int row0 = blockIdx.y * 128;
    const int col0 = blockIdx.x * 128;
    const bool wvalid = OUTBF16 ? true : ((row0 + warp_m * 32) < Mstore);

    wmma::fragment<wmma::accumulator, 16, 16, 8, float> acc[2][4];
#pragma unroll
    for (int i = 0; i < 2; i++)
#pragma unroll
        for (int j = 0; j < 4; j++)
            wmma::load_matrix_sync(acc[i][j],
                brep + col0 + warp_n * 64 + j * 16, 256, wmma::mem_row_major);

    const int am  = tid >> 3;
    const int af4 = tid & 7;
    const int bk  = tid >> 5;
    const int bn4 = tid & 31;
    const int iters = K >> 5;

    auto prefetch = [&](int k0, int st) {
#pragma unroll
        for (int it = 0; it < 4; it++) {
            int m = am + it * 32;
            int r = row0 + m;
            cp16(&As[st * AS_STAGE + m * AS_STRIDE + af4 * 4],
                 A + (size_t)r * K + k0 + af4 * 4, (r < M) ? 16 : 0);
        }
#pragma unroll
        for (int it = 0; it < 4; it++) {
            int k = bk + it * 8;
            cp16(&Bsm[st * BS_STAGE + k * BS_STRIDE + bn4 * 4],
                 B + (size_t)(k0 + k) * N + col0 + bn4 * 4, 16);
        }
        asm volatile("cp.async.commit_group;\n");
    };

    prefetch(0, 0);

    for (int i = 0; i < iters; i++) {
        if (i + 1 < iters) {
            prefetch((i + 1) << 5, (i + 1) & 1);
            asm volatile("cp.async.wait_group 1;\n");
        } else {
            asm volatile("cp.async.wait_group 0;\n");
        }
        __syncthreads();

        const float* as = As + (i & 1) * AS_STAGE;
        const float* bs = Bsm + (i & 1) * BS_STAGE;

#pragma unroll
        for (int kk = 0; kk < 4; kk++) {
            wmma::fragment<wmma::matrix_a, 16, 16, 8, wmma::precision::tf32, wmma::row_major> a[2];
            wmma::fragment<wmma::matrix_b, 16, 16, 8, wmma::precision::tf32, wmma::row_major> b[4];
#pragma unroll
            for (int ii = 0; ii < 2; ii++)
                wmma::load_matrix_sync(a[ii], as + (warp_m * 32 + ii * 16) * AS_STRIDE + kk * 8, AS_STRIDE);
#pragma unroll
            for (int j = 0; j < 4; j++)
                wmma::load_matrix_sync(b[j], bs + (kk * 8) * BS_STRIDE + warp_n * 64 + j * 16, BS_STRIDE);
            // No __float_to_tf32: tensor core reads only the tf32 bits (RZ).
#pragma unroll
            for (int ii = 0; ii < 2; ii++)
#pragma unroll
                for (int j = 0; j < 4; j++)
                    wmma::mma_sync(acc[ii][j], a[ii], b[j], acc[ii][j]);
        }
        __syncthreads();
    }
    // (loop ended with __syncthreads — smem reusable as epilogue scratch)

    if (OUTBF16) {
        // Per-warp 16x16 scratch; convert each fragment tile to bf16.
        float* scratch = sm + wid * 256;
#pragma unroll
        for (int i = 0; i < 2; i++)
#pragma unroll
            for (int j = 0; j < 4; j++) {
                __syncwarp();
                wmma::store_matrix_sync(scratch, acc[i][j], 16, wmma::mem_row_major);
                __syncwarp();
                int r = lane >> 1, cb = (lane & 1) * 8;
                const float* sp = scratch + r * 16 + cb;
                float4 f0 = *(const float4*)sp;
                float4 f1 = *(const float4*)(sp + 4);
                uint4 o;
                __nv_bfloat162 t0 = __floats2bfloat162_rn(f0.x, f0.y);
                __nv_bfloat162 t1 = __floats2bfloat162_rn(f0.z, f0.w);
                __nv_bfloat162 t2 = __floats2bfloat162_rn(f1.x, f1.y);
                __nv_bfloat162 t3 = __floats2bfloat162_rn(f1.z, f1.w);
                o.x = *(uint32_t*)&t0; o.y = *(uint32_t*)&t1;
                o.z = *(uint32_t*)&t2; o.w = *(uint32_t*)&t3;
                int grow = row0 + warp_m * 32 + i * 16 + r;
                int gcol = col0 + warp_n * 64 + j * 16 + cb;
                *(uint4*)(Cb + (size_t)grow * N + gcol) = o;
            }
        return;
    }

    if (wvalid) {
#pragma unroll
        for (int i = 0; i < 2; i++)
#pragma unroll
            for (int j = 0; j < 4; j++) {
                float* cp = C + (size_t)(row0 + warp_m * 32 + i * 16) * N + col0 + warp_n * 64 + j * 16;
                if (resid) {
                    wmma::fragment<wmma::accumulator, 16, 16, 8, float> r;
                    wmma::load_matrix_sync(r,
                        resid + (size_t)(row0 + warp_m * 32 + i * 16) * N + col0 + warp_n * 64 + j * 16,
                        N, wmma::mem_row_major);
#pragma unroll
                    for (int t = 0; t < r.num_elements; t++)
                        acc[i][j].x[t] += r.x[t];
                }
                wmma::store_matrix_sync(cp, acc[i][j], N, wmma::mem_row_major);
            }
    }
}

// ---------------------------------------------------------------------------
// Fused sampling: one warp per (b,q,h).
// Phase 1 (lanes 0-15): warp softmax over 16 logits, lane p computes point
//   p's clamped corner indices + validity-masked weights -> 512B smem/warp.
// Phase 2 (all lanes, lane = channel): 16-point gather, 4 coalesced 64B bf16
//   corner loads + 4 FMA per point.
// ---------------------------------------------------------------------------
__global__ __launch_bounds__(256)
void sample_fused(const float* __restrict__ refp)
{
    __shared__ float meta[8][16][8];

    int gt   = blockIdx.x * blockDim.x + threadIdx.x;
    int warp = gt >> 5;
    int lane = gt & 31;
    int wloc = threadIdx.x >> 5;
    if (warp >= MQ * NH) return;

    int h  = warp & 7;
    int bq = warp >> 3;
    int b  = bq / NQ;

    // Warp softmax over the 16 (level, point) logits
    const float* awp = g_aw + bq * 128 + h * 16;
    float a = (lane < 16) ? awp[lane] : -1e30f;
    float m = a;
#pragma unroll
    for (int o = 8; o; o >>= 1) m = fmaxf(m, __shfl_xor_sync(0xffffffffu, m, o));
    float e = __expf(a - m);
    float s = e;
#pragma unroll
    for (int o = 8; o; o >>= 1) s += __shfl_xor_sync(0xffffffffu, s, o);

    if (lane < 16) {
        const float wp = e / s;
        const int p = lane, l = p >> 2;
        const int W = (0x0D193264 >> (l * 8)) & 0xFF;               // 100,50,25,13
        const long long spack = 0LL | (10000LL << 14) | (12500LL << 28) | (13125LL << 42);
        const int START = (int)((spack >> (14 * l)) & 0x3FFF);      // 0,10000,12500,13125

        const float* offp = g_off + bq * 256 + h * 32;
        float rx = refp[bq * 8 + 2 * l];
        float ry = refp[bq * 8 + 2 * l + 1];

        float x = fmaf(rx, (float)W, offp[2 * p]) - 0.5f;
        float y = fmaf(ry, (float)W, offp[2 * p + 1]) - 0.5f;
        float xf = floorf(x), yf = floorf(y);
        int   x0 = (int)xf,  y0 = (int)yf;
        float wx1 = x - xf, wy1 = y - yf;
        float wx0 = 1.f - wx1, wy0 = 1.f - wy1;

        // padding_mode='zeros': fold OOB validity into the weights
        wx0 *= (float)(x0 >= 0 && x0 < W);
        wx1 *= (float)(x0 >= -1 && x0 < W - 1);
        wy0 *= (float)(y0 >= 0 && y0 < W);
        wy1 *= (float)(y0 >= -1 && y0 < W - 1);

        int xc0 = min(max(x0, 0), W - 1);
        int xc1 = min(max(x0 + 1, 0), W - 1);
        int yc0 = min(max(y0, 0), W - 1);
        int yc1 = min(max(y0 + 1, 0), W - 1);

        const int base = b * NV + START;
        const int hh = h * HD;
        int r0 = (base + yc0 * W) << 8;
        int r1 = (base + yc1 * W) << 8;

        int4 ii;
        ii.x = r0 + (xc0 << 8) + hh;
        ii.y = r0 + (xc1 << 8) + hh;
        ii.z = r1 + (xc0 << 8) + hh;
        ii.w = r1 + (xc1 << 8) + hh;
        *(int4*)&meta[wloc][p][0] = ii;
        *(float4*)&meta[wloc][p][4] =
            make_float4(wp * wy0 * wx0, wp * wy0 * wx1, wp * wy1 * wx0, wp * wy1 * wx1);
    }
    __syncwarp();

    const __nv_bfloat16* vb = g_vb;
    float acc = 0.f;
#pragma unroll
    for (int pt = 0; pt < 16; pt++) {
        int4   ii = *(const int4*)&meta[wloc][pt][0];
        float4 ww = *(const float4*)&meta[wloc][pt][4];
        acc = fmaf(ww.x, __bfloat162float(vb[ii.x + lane]), acc);
        acc = fmaf(ww.y, __bfloat162float(vb[ii.y + lane]), acc);
        acc = fmaf(ww.z, __bfloat162float(vb[ii.z + lane]), acc);
        acc = fmaf(ww.w, __bfloat162float(vb[ii.w + lane]), acc);
    }
    g_mid[bq * 256 + h * HD + lane] = acc;
}

// ---------------------------------------------------------------------------
extern "C" void kernel_launch(void* const* d_in, const int* in_sizes, int n_in,
                              void* d_out, int out_size)
{
    const float* query  = (const float*)d_in[0];
    const float* value  = (const float*)d_in[1];
    const float* refp   = (const float*)d_in[2];
    const float* W_off  = (const float*)d_in[3];
    const float* b_off  = (const float*)d_in[4];
    const float* W_attn = (const float*)d_in[5];
    const float* b_attn = (const float*)d_in[6];
    const float* W_val  = (const float*)d_in[7];
    const float* b_val  = (const float*)d_in[8];
    const float* W_out  = (const float*)d_in[9];
    const float* b_out  = (const float*)d_in[10];
    float* out = (float*)d_out;

    float *poff, *paw, *pmid, *pbrep;
    __nv_bfloat16* pvb;
    cudaGetSymbolAddress((void**)&pvb,   g_vb);
    cudaGetSymbolAddress((void**)&poff,  g_off);
    cudaGetSymbolAddress((void**)&paw,   g_aw);
    cudaGetSymbolAddress((void**)&pmid,  g_mid);
    cudaGetSymbolAddress((void**)&pbrep, g_brep);

    cudaFuncSetAttribute(gemm_tf32<0>, cudaFuncAttributeMaxDynamicSharedMemorySize, GEMM_SMEM);
    cudaFuncSetAttribute(gemm_tf32<1>, cudaFuncAttributeMaxDynamicSharedMemorySize, GEMM_SMEM);

    // 0) replicated bias tiles
    fill_brep<<<64, 256>>>(b_val, b_off, b_attn, b_out);

    // 1) value projection -> bf16 cache directly (fused epilogue convert)
    gemm_tf32<1><<<dim3(2, MV_PAD / 128), 256, GEMM_SMEM>>>(
        value, W_val, pbrep + 0 * 4096, nullptr, nullptr, pvb, MV, 256, 256, MV_PAD);

    // 2) sampling-offset projection
    gemm_tf32<0><<<dim3(2, MQ_PAD / 128), 256, GEMM_SMEM>>>(
        query, W_off, pbrep + 1 * 4096, nullptr, poff, nullptr, MQ, 256, 256, MQ_PAD);

    // 3) attention-weight projection (N=128)
    gemm_tf32<0><<<dim3(1, MQ_PAD / 128), 256, GEMM_SMEM>>>(
        query, W_attn, pbrep + 2 * 4096, nullptr, paw, nullptr, MQ, 128, 256, MQ_PAD);

    // 4) fused softmax + position precompute + warp gather
    sample_fused<<<(MQ * NH * 32 + 255) / 256, 256>>>(refp);

    // 5) output projection + bias + fp32 residual
    gemm_tf32<0><<<dim3(2, MQ_PAD / 128), 256, GEMM_SMEM>>>(
        pmid, W_out, pbrep + 3 * 4096, query, out, nullptr, MQ, 256, 256, MQ);
}

// round 8
// speedup vs baseline: 2.2445x; 1.1559x over previous
#include <cuda_runtime.h>
#include <cuda_bf16.h>
#include <mma.h>
#include <math.h>
#include <stdint.h>

using namespace nvcuda;

#define BS 4
#define NQ 6000
#define NV 13294
#define EMB 256
#define NH 8
#define HD 32

#define MV (BS * NV)          // 53176
#define MQ (BS * NQ)          // 24000
#define MV_PAD 53248          // 416 * 128
#define MQ_PAD 24064          // 188 * 128

// tile counts for the batched input GEMM
#define T_VAL 832             // (MV_PAD/128) * 2
#define T_OFF 376             // (MQ_PAD/128) * 2
#define T_AW  188             // (MQ_PAD/128) * 1
#define T_ALL (T_VAL + T_OFF + T_AW)   // 1396

// Scratch (device globals: allocation-free per harness rules).
__device__ __nv_bfloat16 g_vb [(size_t)MV_PAD * EMB];   // value proj bf16 (gather source)
__device__ float         g_off[(size_t)MQ_PAD * 256];   // sampling offsets
__device__ float         g_aw [(size_t)MQ_PAD * 128];   // attn logits
__device__ float         g_mid[(size_t)MQ_PAD * 256];   // aggregated heads
__device__ float         g_brep[4 * 16 * 256];          // 16-row-replicated bias tiles

// ---------------------------------------------------------------------------
// Replicated bias tiles (16 identical rows) seeding GEMM accumulators.
// tile 0: b_val, 1: b_off, 2: b_attn (N=128), 3: b_out
// ---------------------------------------------------------------------------
__global__ void fill_brep(const float* __restrict__ b0, const float* __restrict__ b1,
                          const float* __restrict__ b2, const float* __restrict__ b3)
{
    int i = blockIdx.x * blockDim.x + threadIdx.x;
    if (i >= 4 * 16 * 256) return;
    int t = i >> 12;
    int c = i & 255;
    const float* b = (t == 0) ? b0 : (t == 1) ? b1 : (t == 2) ? b2 : b3;
    g_brep[i] = (t == 2) ? b[c & 127] : b[c];
}

// ---------------------------------------------------------------------------
// Shared GEMM machinery: tf32 wmma, cp.async double-buffered, BK=32,
// 128x128 block tile, 256 threads = 8 warps (4x2), warp tile 32x64.
// No explicit f32->tf32 (HW reads tf32 bits; RZ truncation).
// ---------------------------------------------------------------------------
#define AS_STRIDE 40
#define BS_STRIDE 136
#define AS_STAGE (128 * AS_STRIDE)
#define BS_STAGE (32 * BS_STRIDE)
#define GEMM_SMEM ((2 * AS_STAGE + 2 * BS_STAGE) * 4)   // 75776 bytes

__device__ __forceinline__ void cp16(float* dst_smem, const float* src, int src_bytes)
{
    uint32_t d = (uint32_t)__cvta_generic_to_shared(dst_smem);
    asm volatile("cp.async.cg.shared.global [%0], [%1], 16, %2;\n"
                 :: "r"(d), "l"(src), "r"(src_bytes));
}

struct GemmCore {
    float* As; float* Bsm;
    int tid, lane, wid, warp_m, warp_n, row0, col0;
    wmma::fragment<wmma::accumulator, 16, 16, 8, float> acc[2][4];

    __device__ __forceinline__ void init(float* sm, int r0, int c0, const float* brep)
    {
        As = sm; Bsm = sm + 2 * AS_STAGE;
        tid = threadIdx.x; lane = tid & 31; wid = tid >> 5;
        warp_m = wid >> 1; warp_n = wid & 1;
        row0 = r0; col0 = c0;
#pragma unroll
        for (int i = 0; i < 2; i++)
#pragma unroll
            for (int j = 0; j < 4; j++)
                wmma::load_matrix_sync(acc[i][j],
                    brep + col0 + warp_n * 64 + j * 16, 256, wmma::mem_row_major);
    }

    __device__ __forceinline__ void prefetch(const float* A, const float* B,
                                             int M, int N, int K, int k0, int st)
    {
        const int am  = tid >> 3, af4 = tid & 7;
        const int bk  = tid >> 5, bn4 = tid & 31;
#pragma unroll
        for (int it = 0; it < 4; it++) {
            int m = am + it * 32;
            int r = row0 + m;
            cp16(&As[st * AS_STAGE + m * AS_STRIDE + af4 * 4],
                 A + (size_t)r * K + k0 + af4 * 4, (r < M) ? 16 : 0);
        }
#pragma unroll
        for (int it = 0; it < 4; it++) {
            int k = bk + it * 8;
            cp16(&Bsm[st * BS_STAGE + k * BS_STRIDE + bn4 * 4],
                 B + (size_t)(k0 + k) * N + col0 + bn4 * 4, 16);
        }
        asm volatile("cp.async.commit_group;\n");
    }

    __device__ __forceinline__ void mainloop(const float* A, const float* B,
                                             int M, int N, int K)
    {
        const int iters = K >> 5;
        prefetch(A, B, M, N, K, 0, 0);
        for (int i = 0; i < iters; i++) {
            if (i + 1 < iters) {
                prefetch(A, B, M, N, K, (i + 1) << 5, (i + 1) & 1);
                asm volatile("cp.async.wait_group 1;\n");
            } else {
                asm volatile("cp.async.wait_group 0;\n");
            }
            __syncthreads();
            const float* as = As + (i & 1) * AS_STAGE;
            const float* bs = Bsm + (i & 1) * BS_STAGE;
#pragma unroll
            for (int kk = 0; kk < 4; kk++) {
                wmma::fragment<wmma::matrix_a, 16, 16, 8, wmma::precision::tf32, wmma::row_major> a[2];
                wmma::fragment<wmma::matrix_b, 16, 16, 8, wmma::precision::tf32, wmma::row_major> b[4];
#pragma unroll
                for (int ii = 0; ii < 2; ii++)
                    wmma::load_matrix_sync(a[ii], as + (warp_m * 32 + ii * 16) * AS_STRIDE + kk * 8, AS_STRIDE);
#pragma unroll
                for (int j = 0; j < 4; j++)
                    wmma::load_matrix_sync(b[j], bs + (kk * 8) * BS_STRIDE + warp_n * 64 + j * 16, BS_STRIDE);
#pragma unroll
                for (int ii = 0; ii < 2; ii++)
#pragma unroll
                    for (int j = 0; j < 4; j++)
                        wmma::mma_sync(acc[ii][j], a[ii], b[j], acc[ii][j]);
            }
            __syncthreads();
        }
    }

    __device__ __forceinline__ void store_f32(float* C, const float* resid, int N, int Mstore)
    {
        if ((row0 + warp_m * 32) >= Mstore) return;
#pragma unroll
        for (int i = 0; i < 2; i++)
#pragma unroll
            for (int j = 0; j < 4; j++) {
                size_t off = (size_t)(row0 + warp_m * 32 + i * 16) * N + col0 + warp_n * 64 + j * 16;
                if (resid) {
                    wmma::fragment<wmma::accumulator, 16, 16, 8, float> r;
                    wmma::load_matrix_sync(r, resid + off, N, wmma::mem_row_major);
#pragma unroll
                    for (int t = 0; t < r.num_elements; t++)
                        acc[i][j].x[t] += r.x[t];
                }
                wmma::store_matrix_sync(C + off, acc[i][j], N, wmma::mem_row_major);
            }
    }

    __device__ __forceinline__ void store_bf16(__nv_bfloat16* Cb, int N, float* sm)
    {
        float* scratch = sm + wid * 256;
#pragma unroll
        for (int i = 0; i < 2; i++)
#pragma unroll
            for (int j = 0; j < 4; j++) {
                __syncwarp();
                wmma::store_matrix_sync(scratch, acc[i][j], 16, wmma::mem_row_major);
                __syncwarp();
                int r = lane >> 1, cb = (lane & 1) * 8;
                const float* sp = scratch + r * 16 + cb;
                float4 f0 = *(const float4*)sp;
                float4 f1 = *(const float4*)(sp + 4);
                uint4 o;
                __nv_bfloat162 t0 = __floats2bfloat162_rn(f0.x, f0.y);
                __nv_bfloat162 t1 = __floats2bfloat162_rn(f0.z, f0.w);
                __nv_bfloat162 t2 = __floats2bfloat162_rn(f1.x, f1.y);
                __nv_bfloat162 t3 = __floats2bfloat162_rn(f1.z, f1.w);
                o.x = *(uint32_t*)&t0; o.y = *(uint32_t*)&t1;
                o.z = *(uint32_t*)&t2; o.w = *(uint32_t*)&t3;
                int grow = row0 + warp_m * 32 + i * 16 + r;
                int gcol = col0 + warp_n * 64 + j * 16 + cb;
                *(uint4*)(Cb + (size_t)grow * N + gcol) = o;
            }
    }
};

// ---------------------------------------------------------------------------
// Batched input GEMM: one flat grid covering 3 independent problems
//   tiles [0, 832):        g_vb  = value @ W_val + b_val  (bf16 epilogue)
//   tiles [832, 1208):     g_off = query @ W_off + b_off
//   tiles [1208, 1396):    g_aw  = query @ W_attn + b_attn (N=128)
// ---------------------------------------------------------------------------
__global__ __launch_bounds__(256, 2)
void gemm_batched(const float* __restrict__ value, const float* __restrict__ query,
                  const float* __restrict__ W_val, const float* __restrict__ W_off,
                  const float* __restrict__ W_attn, const float* __restrict__ brep)
{
    extern __shared__ float sm[];
    int t = blockIdx.x;

    const float *A, *B, *brp;
    int M, N, row_t, col_t, prob;
    if (t < T_VAL) {
        prob = 0; A = value; B = W_val; brp = brep;
        M = MV; N = 256; row_t = t >> 1; col_t = t & 1;
    } else if (t < T_VAL + T_OFF) {
        int u = t - T_VAL;
        prob = 1; A = query; B = W_off; brp = brep + 4096;
        M = MQ; N = 256; row_t = u >> 1; col_t = u & 1;
    } else {
        int u = t - T_VAL - T_OFF;
        prob = 2; A = query; B = W_attn; brp = brep + 2 * 4096;
        M = MQ; N = 128; row_t = u; col_t = 0;
    }

    GemmCore g;
    g.init(sm, row_t * 128, col_t * 128, brp);
    g.mainloop(A, B, M, N, 256);

    if (prob == 0)       g.store_bf16(g_vb, 256, sm);
    else if (prob == 1)  g.store_f32(g_off, nullptr, 256, MQ_PAD);
    else                 g.store_f32(g_aw,  nullptr, 128, MQ_PAD);
}

// ---------------------------------------------------------------------------
// Output projection + bias + fp32 residual (separate: depends on sampler)
// ---------------------------------------------------------------------------
__global__ __launch_bounds__(256, 2)
void gemm_out(const float* __restrict__ brep, const float* __restrict__ query,
              float* __restrict__ out)
{
    extern __shared__ float sm[];
    GemmCore g;
    g.init(sm, blockIdx.y * 128, blockIdx.x * 128, brep + 3 * 4096);
    g.mainloop(g_mid, nullptr, MQ, 256, 256);
    g.store_f32(out, query, 256, MQ);
}
// gemm_out needs B pointer — specialization of mainloop requires B; use W_out via param
__global__ __launch_bounds__(256, 2)
void gemm_out2(const float* __restrict__ W_out, const float* __restrict__ brep,
               const float* __restrict__ query, float* __restrict__ out)
{
    extern __shared__ float sm[];
    GemmCore g;
    g.init(sm, blockIdx.y * 128, blockIdx.x * 128, brep + 3 * 4096);
    g.mainloop(g_mid, W_out, MQ, 256, 256);
    g.store_f32(out, query, 256, MQ);
}

// ---------------------------------------------------------------------------
// Fused sampling: one warp per (b,q,h).
// Phase 1 (lanes 0-15): warp softmax + per-point corner indices/weights -> smem.
// Phase 2: corner-per-lane-group gather. group g = lane>>3 handles corner g,
//   each lane loads 8B (4 channels) -> ONE LDG.64 per point per warp (vs 4x u16
//   pattern). Per-group weighted accumulation; cross-group shfl reduction at
//   the end; lanes 0-7 store one float4 each.
// ---------------------------------------------------------------------------
__global__ __launch_bounds__(256)
void sample_fused(const float* __restrict__ refp)
{
    __shared__ float meta[8][16][8];

    int gt   = blockIdx.x * blockDim.x + threadIdx.x;
    int warp = gt >> 5;
    int lane = gt & 31;
    int wloc = threadIdx.x >> 5;
    if (warp >= MQ * NH) return;

    int h  = warp & 7;
    int bq = warp >> 3;
    int b  = bq / NQ;

    // Warp softmax over the 16 (level, point) logits
    const float* awp = g_aw + bq * 128 + h * 16;
    float a = (lane < 16) ? awp[lane] : -1e30f;
    float m = a;
#pragma unroll
    for (int o = 8; o; o >>= 1) m = fmaxf(m, __shfl_xor_sync(0xffffffffu, m, o));
    float e = __expf(a - m);
    float s = e;
#pragma unroll
    for (int o = 8; o; o >>= 1) s += __shfl_xor_sync(0xffffffffu, s, o);

    if (lane < 16) {
        const float wp = e / s;
        const int p = lane, l = p >> 2;
        const int W = (0x0D193264 >> (l * 8)) & 0xFF;               // 100,50,25,13
        const long long spack = 0LL | (10000LL << 14) | (12500LL << 28) | (13125LL << 42);
        const int START = (int)((spack >> (14 * l)) & 0x3FFF);      // 0,10000,12500,13125

        const float* offp = g_off + bq * 256 + h * 32;
        float rx = refp[bq * 8 + 2 * l];
        float ry = refp[bq * 8 + 2 * l + 1];

        float x = fmaf(rx, (float)W, offp[2 * p]) - 0.5f;
        float y = fmaf(ry, (float)W, offp[2 * p + 1]) - 0.5f;
        float xf = floorf(x), yf = floorf(y);
        int   x0 = (int)xf,  y0 = (int)yf;
        float wx1 = x - xf, wy1 = y - yf;
        float wx0 = 1.f - wx1, wy0 = 1.f - wy1;

        // padding_mode='zeros': fold OOB validity into the weights
        wx0 *= (float)(x0 >= 0 && x0 < W);
        wx1 *= (float)(x0 >= -1 && x0 < W - 1);
        wy0 *= (float)(y0 >= 0 && y0 < W);
        wy1 *= (float)(y0 >= -1 && y0 < W - 1);

        int xc0 = min(max(x0, 0), W - 1);
        int xc1 = min(max(x0 + 1, 0), W - 1);
        int yc0 = min(max(y0, 0), W - 1);
        int yc1 = min(max(y0 + 1, 0), W - 1);

        const int base = b * NV + START;
        const int hh = h * HD;
        int r0 = (base + yc0 * W) << 8;
        int r1 = (base + yc1 * W) << 8;

        int4 ii;
        ii.x = r0 + (xc0 << 8) + hh;
        ii.y = r0 + (xc1 << 8) + hh;
        ii.z = r1 + (xc0 << 8) + hh;
        ii.w = r1 + (xc1 << 8) + hh;
        *(int4*)&meta[wloc][p][0] = ii;
        *(float4*)&meta[wloc][p][4] =
            make_float4(wp * wy0 * wx0, wp * wy0 * wx1, wp * wy1 * wx0, wp * wy1 * wx1);
    }
    __syncwarp();

    const int grp = lane >> 3;          // corner 0..3
    const int sub = lane & 7;           // channel quad 0..7
    const __nv_bfloat16* vb = g_vb;

    float a0 = 0.f, a1 = 0.f, a2 = 0.f, a3 = 0.f;
#pragma unroll
    for (int pt = 0; pt < 16; pt++) {
        int   idx = ((const int*)&meta[wloc][pt][0])[grp];
        float w   = meta[wloc][pt][4 + grp];
        uint2 raw = *(const uint2*)(vb + idx + sub * 4);
        __nv_bfloat162 p0 = *(__nv_bfloat162*)&raw.x;
        __nv_bfloat162 p1 = *(__nv_bfloat162*)&raw.y;
        float2 f0 = __bfloat1622float2(p0);
        float2 f1 = __bfloat1622float2(p1);
        a0 = fmaf(w, f0.x, a0);
        a1 = fmaf(w, f0.y, a1);
        a2 = fmaf(w, f1.x, a2);
        a3 = fmaf(w, f1.y, a3);
    }
    // reduce across the 4 corner groups (xor 8, 16)
#pragma unroll
    for (int o = 8; o <= 16; o <<= 1) {
        a0 += __shfl_xor_sync(0xffffffffu, a0, o);
        a1 += __shfl_xor_sync(0xffffffffu, a1, o);
        a2 += __shfl_xor_sync(0xffffffffu, a2, o);
        a3 += __shfl_xor_sync(0xffffffffu, a3, o);
    }
    if (grp == 0)
        *(float4*)&g_mid[bq * 256 + h * HD + sub * 4] = make_float4(a0, a1, a2, a3);
}

// ---------------------------------------------------------------------------
extern "C" void kernel_launch(void* const* d_in, const int* in_sizes, int n_in,
                              void* d_out, int out_size)
{
    const float* query  = (const float*)d_in[0];
    const float* value  = (const float*)d_in[1];
    const float* refp   = (const float*)d_in[2];
    const float* W_off  = (const float*)d_in[3];
    const float* b_off  = (const float*)d_in[4];
    const float* W_attn = (const float*)d_in[5];
    const float* b_attn = (const float*)d_in[6];
    const float* W_val  = (const float*)d_in[7];
    const float* b_val  = (const float*)d_in[8];
    const float* W_out  = (const float*)d_in[9];
    const float* b_out  = (const float*)d_in[10];
    float* out = (float*)d_out;

    float* pbrep;
    cudaGetSymbolAddress((void**)&pbrep, g_brep);

    cudaFuncSetAttribute(gemm_batched, cudaFuncAttributeMaxDynamicSharedMemorySize, GEMM_SMEM);
    cudaFuncSetAttribute(gemm_out2,    cudaFuncAttributeMaxDynamicSharedMemorySize, GEMM_SMEM);

    // 0) replicated bias tiles
    fill_brep<<<64, 256>>>(b_val, b_off, b_attn, b_out);

    // 1) all three input projections in one flat-grid launch
    gemm_batched<<<T_ALL, 256, GEMM_SMEM>>>(value, query, W_val, W_off, W_attn, pbrep);

    // 2) fused softmax + position precompute + grouped-corner gather
    sample_fused<<<(MQ * NH * 32 + 255) / 256, 256>>>(refp);

    // 3) output projection + bias + fp32 residual
    gemm_out2<<<dim3(2, MQ_PAD / 128), 256, GEMM_SMEM>>>(W_out, pbrep, query, out);
}

// round 9
// speedup vs baseline: 3.3989x; 1.5143x over previous
#include <cuda_runtime.h>
#include <cuda_bf16.h>
#include <mma.h>
#include <math.h>
#include <stdint.h>

using namespace nvcuda;

#define BS 4
#define NQ 6000
#define NV 13294
#define EMB 256
#define NH 8
#define HD 32

#define MV (BS * NV)          // 53176
#define MQ (BS * NQ)          // 24000
#define MV_PAD 53248          // 416 * 128
#define MQ_PAD 24064          // 188 * 128

// tile counts for the batched input GEMM
#define T_VAL 832             // (MV_PAD/128) * 2
#define T_OFF 376             // (MQ_PAD/128) * 2
#define T_AW  188             // (MQ_PAD/128) * 1
#define T_ALL (T_VAL + T_OFF + T_AW)   // 1396

// Scratch (device globals: allocation-free per harness rules).
__device__ __nv_bfloat16 g_valb[(size_t)MV_PAD * EMB];  // value, bf16
__device__ __nv_bfloat16 g_qb  [(size_t)MQ_PAD * EMB];  // query, bf16
__device__ __nv_bfloat16 g_wv  [256 * 256];             // W_val  bf16
__device__ __nv_bfloat16 g_wof [256 * 256];             // W_off  bf16
__device__ __nv_bfloat16 g_wat [256 * 128];             // W_attn bf16
__device__ __nv_bfloat16 g_wo  [256 * 256];             // W_out  bf16
__device__ __nv_bfloat16 g_vb  [(size_t)MV_PAD * EMB];  // value proj (gather source)
__device__ float         g_off [(size_t)MQ_PAD * 256];  // sampling offsets
__device__ float         g_aw  [(size_t)MQ_PAD * 128];  // attn logits
__device__ __nv_bfloat16 g_mid [(size_t)MQ_PAD * 256];  // aggregated heads (bf16)
__device__ float         g_brep[4 * 16 * 256];          // 16-row-replicated bias tiles

// ---------------------------------------------------------------------------
// Replicated bias tiles (16 identical rows) seeding GEMM accumulators.
// tile 0: b_val, 1: b_off, 2: b_attn (N=128), 3: b_out
// ---------------------------------------------------------------------------
__global__ void fill_brep(const float* __restrict__ b0, const float* __restrict__ b1,
                          const float* __restrict__ b2, const float* __restrict__ b3)
{
    int i = blockIdx.x * blockDim.x + threadIdx.x;
    if (i >= 4 * 16 * 256) return;
    int t = i >> 12;
    int c = i & 255;
    const float* b = (t == 0) ? b0 : (t == 1) ? b1 : (t == 2) ? b2 : b3;
    g_brep[i] = (t == 2) ? b[c & 127] : b[c];
}

// ---------------------------------------------------------------------------
// fp32 -> bf16 conversion of all GEMM operands (one fused pass).
// float4 granularity; segments: value, query, W_val, W_off, W_attn, W_out.
// ---------------------------------------------------------------------------
#define S_VAL (MV * 64)
#define S_QRY (MQ * 64)
#define S_W   16384
#define S_WA  8192
#define S_TOT (S_VAL + S_QRY + 3 * S_W + S_WA)   // 4,996,608

__global__ void cvt_all(const float* __restrict__ value, const float* __restrict__ query,
                        const float* __restrict__ Wv, const float* __restrict__ Wof,
                        const float* __restrict__ Wat, const float* __restrict__ Wo)
{
    int i = blockIdx.x * blockDim.x + threadIdx.x;
    if (i >= S_TOT) return;
    const float* src; __nv_bfloat16* dst;
    int j = i;
    if (j < S_VAL) { src = value; dst = g_valb; }
    else { j -= S_VAL;
        if (j < S_QRY) { src = query; dst = g_qb; }
        else { j -= S_QRY;
            if (j < S_W) { src = Wv; dst = g_wv; }
            else { j -= S_W;
                if (j < S_W) { src = Wof; dst = g_wof; }
                else { j -= S_W;
                    if (j < S_WA) { src = Wat; dst = g_wat; }
                    else { j -= S_WA; src = Wo; dst = g_wo; } } } } }
    float4 v = ((const float4*)src)[j];
    __nv_bfloat162 t0 = __floats2bfloat162_rn(v.x, v.y);
    __nv_bfloat162 t1 = __floats2bfloat162_rn(v.z, v.w);
    uint2 o; o.x = *(uint32_t*)&t0; o.y = *(uint32_t*)&t1;
    ((uint2*)dst)[j] = o;
}

// ---------------------------------------------------------------------------
// bf16 tensor-core GEMM core: wmma m16n16k16, cp.async double-buffered,
// BK=64, 128x128 block tile, 256 threads = 8 warps (4x2), warp tile 32x64.
// Accumulators fp32, seeded from replicated bias tile.
// ---------------------------------------------------------------------------
#define AROW 72                    // A smem row stride (bf16 elems, 16B-aligned pad)
#define BROW 136                   // B smem row stride
#define A_ST (128 * AROW)          // 9216 bf16 per A stage
#define B_ST (64 * BROW)           // 8704 bf16 per B stage
#define GEMM_SMEM ((2 * A_ST + 2 * B_ST) * 2)   // 71680 bytes

__device__ __forceinline__ void cp16(void* dst_smem, const void* src, int src_bytes)
{
    uint32_t d = (uint32_t)__cvta_generic_to_shared(dst_smem);
    asm volatile("cp.async.cg.shared.global [%0], [%1], 16, %2;\n"
                 :: "r"(d), "l"(src), "r"(src_bytes));
}

struct GemmCore {
    __nv_bfloat16* As; __nv_bfloat16* Bsm;
    int tid, lane, wid, warp_m, warp_n, row0, col0;
    wmma::fragment<wmma::accumulator, 16, 16, 16, float> acc[2][4];

    __device__ __forceinline__ void init(char* sm, int r0, int c0, const float* brep)
    {
        As = (__nv_bfloat16*)sm; Bsm = As + 2 * A_ST;
        tid = threadIdx.x; lane = tid & 31; wid = tid >> 5;
        warp_m = wid >> 1; warp_n = wid & 1;
        row0 = r0; col0 = c0;
#pragma unroll
        for (int i = 0; i < 2; i++)
#pragma unroll
            for (int j = 0; j < 4; j++)
                wmma::load_matrix_sync(acc[i][j],
                    brep + col0 + warp_n * 64 + j * 16, 256, wmma::mem_row_major);
    }

    __device__ __forceinline__ void prefetch(const __nv_bfloat16* A, const __nv_bfloat16* B,
                                             int M, int N, int K, int k0, int st)
    {
        const int am = tid >> 3, ac = tid & 7;     // A: row base, 16B chunk (8 bf16)
        const int bk = tid >> 4, bc = tid & 15;    // B: k base, 16B chunk
#pragma unroll
        for (int it = 0; it < 4; it++) {
            int m = am + it * 32;
            int r = row0 + m;
            cp16(&As[st * A_ST + m * AROW + ac * 8],
                 A + (size_t)r * K + k0 + ac * 8, (r < M) ? 16 : 0);
        }
#pragma unroll
        for (int it = 0; it < 4; it++) {
            int k = bk + it * 16;
            cp16(&Bsm[st * B_ST + k * BROW + bc * 8],
                 B + (size_t)(k0 + k) * N + col0 + bc * 8, 16);
        }
        asm volatile("cp.async.commit_group;\n");
    }

    __device__ __forceinline__ void mainloop(const __nv_bfloat16* A, const __nv_bfloat16* B,
                                             int M, int N, int K)
    {
        const int iters = K >> 6;
        prefetch(A, B, M, N, K, 0, 0);
        for (int i = 0; i < iters; i++) {
            if (i + 1 < iters) {
                prefetch(A, B, M, N, K, (i + 1) << 6, (i + 1) & 1);
                asm volatile("cp.async.wait_group 1;\n");
            } else {
                asm volatile("cp.async.wait_group 0;\n");
            }
            __syncthreads();
            const __nv_bfloat16* as = As + (i & 1) * A_ST;
            const __nv_bfloat16* bs = Bsm + (i & 1) * B_ST;
#pragma unroll
            for (int kk = 0; kk < 4; kk++) {
                wmma::fragment<wmma::matrix_a, 16, 16, 16, __nv_bfloat16, wmma::row_major> a[2];
                wmma::fragment<wmma::matrix_b, 16, 16, 16, __nv_bfloat16, wmma::row_major> b[4];
#pragma unroll
                for (int ii = 0; ii < 2; ii++)
                    wmma::load_matrix_sync(a[ii], as + (warp_m * 32 + ii * 16) * AROW + kk * 16, AROW);
#pragma unroll
                for (int j = 0; j < 4; j++)
                    wmma::load_matrix_sync(b[j], bs + (kk * 16) * BROW + warp_n * 64 + j * 16, BROW);
#pragma unroll
                for (int ii = 0; ii < 2; ii++)
#pragma unroll
                    for (int j = 0; j < 4; j++)
                        wmma::mma_sync(acc[ii][j], a[ii], b[j], acc[ii][j]);
            }
            __syncthreads();
        }
    }

    __device__ __forceinline__ void store_f32(float* C, const float* resid, int N, int Mstore)
    {
        if ((row0 + warp_m * 32) >= Mstore) return;
#pragma unroll
        for (int i = 0; i < 2; i++)
#pragma unroll
            for (int j = 0; j < 4; j++) {
                size_t off = (size_t)(row0 + warp_m * 32 + i * 16) * N + col0 + warp_n * 64 + j * 16;
                if (resid) {
                    wmma::fragment<wmma::accumulator, 16, 16, 16, float> r;
                    wmma::load_matrix_sync(r, resid + off, N, wmma::mem_row_major);
#pragma unroll
                    for (int t = 0; t < r.num_elements; t++)
                        acc[i][j].x[t] += r.x[t];
                }
                wmma::store_matrix_sync(C + off, acc[i][j], N, wmma::mem_row_major);
            }
    }

    __device__ __forceinline__ void store_bf16(__nv_bfloat16* Cb, int N, char* sm)
    {
        float* scratch = (float*)sm + wid * 256;   // 8KB total, fits in stage smem
#pragma unroll
        for (int i = 0; i < 2; i++)
#pragma unroll
            for (int j = 0; j < 4; j++) {
                __syncwarp();
                wmma::store_matrix_sync(scratch, acc[i][j], 16, wmma::mem_row_major);
                __syncwarp();
                int r = lane >> 1, cb = (lane & 1) * 8;
                const float* sp = scratch + r * 16 + cb;
                float4 f0 = *(const float4*)sp;
                float4 f1 = *(const float4*)(sp + 4);
                uint4 o;
                __nv_bfloat162 t0 = __floats2bfloat162_rn(f0.x, f0.y);
                __nv_bfloat162 t1 = __floats2bfloat162_rn(f0.z, f0.w);
                __nv_bfloat162 t2 = __floats2bfloat162_rn(f1.x, f1.y);
                __nv_bfloat162 t3 = __floats2bfloat162_rn(f1.z, f1.w);
                o.x = *(uint32_t*)&t0; o.y = *(uint32_t*)&t1;
                o.z = *(uint32_t*)&t2; o.w = *(uint32_t*)&t3;
                int grow = row0 + warp_m * 32 + i * 16 + r;
                int gcol = col0 + warp_n * 64 + j * 16 + cb;
                *(uint4*)(Cb + (size_t)grow * N + gcol) = o;
            }
    }
};

// ---------------------------------------------------------------------------
// Batched input GEMM (bf16): one flat grid covering 3 independent problems
//   tiles [0, 832):     g_vb  = value @ W_val + b_val  (bf16 epilogue)
//   tiles [832, 1208):  g_off = query @ W_off + b_off  (f32)
//   tiles [1208, 1396): g_aw  = query @ W_attn + b_attn (f32, N=128)
// ---------------------------------------------------------------------------
__global__ __launch_bounds__(256, 2)
void gemm_batched(const float* __restrict__ brep)
{
    extern __shared__ char smc[];
    int t = blockIdx.x;

    const __nv_bfloat16 *A, *B;
    const float* brp;
    int M, N, row_t, col_t, prob;
    if (t < T_VAL) {
        prob = 0; A = g_valb; B = g_wv; brp = brep;
        M = MV; N = 256; row_t = t >> 1; col_t = t & 1;
    } else if (t < T_VAL + T_OFF) {
        int u = t - T_VAL;
        prob = 1; A = g_qb; B = g_wof; brp = brep + 4096;
        M = MQ; N = 256; row_t = u >> 1; col_t = u & 1;
    } else {
        int u = t - T_VAL - T_OFF;
        prob = 2; A = g_qb; B = g_wat; brp = brep + 2 * 4096;
        M = MQ; N = 128; row_t = u; col_t = 0;
    }

    GemmCore g;
    g.init(smc, row_t * 128, col_t * 128, brp);
    g.mainloop(A, B, M, N, 256);

    if (prob == 0)       g.store_bf16(g_vb, 256, smc);
    else if (prob == 1)  g.store_f32(g_off, nullptr, 256, MQ_PAD);
    else                 g.store_f32(g_aw,  nullptr, 128, MQ_PAD);
}

// ---------------------------------------------------------------------------
// Output projection + bias + fp32 residual
// ---------------------------------------------------------------------------
__global__ __launch_bounds__(256, 2)
void gemm_out(const float* __restrict__ brep, const float* __restrict__ query,
              float* __restrict__ out)
{
    extern __shared__ char smc[];
    GemmCore g;
    g.init(smc, blockIdx.y * 128, blockIdx.x * 128, brep + 3 * 4096);
    g.mainloop(g_mid, g_wo, MQ, 256, 256);
    g.store_f32(out, query, 256, MQ);
}

// ---------------------------------------------------------------------------
// Fused sampling: one warp per (b,q,h).
// Phase 1 (lanes 0-15): warp softmax + per-point corner indices/weights -> smem.
// Phase 2: corner-per-lane-group gather (grp=lane>>3 handles corner grp, each
//   lane loads 8B = 4 bf16 channels -> one LDG.64 per point per warp), per-group
//   FMA accumulate, cross-group shfl reduction, bf16 store to g_mid.
// ---------------------------------------------------------------------------
__global__ __launch_bounds__(256)
void sample_fused(const float* __restrict__ refp)
{
    __shared__ float meta[8][16][8];

    int gt   = blockIdx.x * blockDim.x + threadIdx.x;
    int warp = gt >> 5;
    int lane = gt & 31;
    int wloc = threadIdx.x >> 5;
    if (warp >= MQ * NH) return;

    int h  = warp & 7;
    int bq = warp >> 3;
    int b  = bq / NQ;

    // Warp softmax over the 16 (level, point) logits
    const float* awp = g_aw + bq * 128 + h * 16;
    float a = (lane < 16) ? awp[lane] : -1e30f;
    float m = a;
#pragma unroll
    for (int o = 8; o; o >>= 1) m = fmaxf(m, __shfl_xor_sync(0xffffffffu, m, o));
    float e = __expf(a - m);
    float s = e;
#pragma unroll
    for (int o = 8; o; o >>= 1) s += __shfl_xor_sync(0xffffffffu, s, o);

    if (lane < 16) {
        const float wp = e / s;
        const int p = lane, l = p >> 2;
        const int W = (0x0D193264 >> (l * 8)) & 0xFF;               // 100,50,25,13
        const long long spack = 0LL | (10000LL << 14) | (12500LL << 28) | (13125LL << 42);
        const int START = (int)((spack >> (14 * l)) & 0x3FFF);      // 0,10000,12500,13125

        const float* offp = g_off + bq * 256 + h * 32;
        float rx = refp[bq * 8 + 2 * l];
        float ry = refp[bq * 8 + 2 * l + 1];

        float x = fmaf(rx, (float)W, offp[2 * p]) - 0.5f;
        float y = fmaf(ry, (float)W, offp[2 * p + 1]) - 0.5f;
        float xf = floorf(x), yf = floorf(y);
        int   x0 = (int)xf,  y0 = (int)yf;
        float wx1 = x - xf, wy1 = y - yf;
        float wx0 = 1.f - wx1, wy0 = 1.f - wy1;

        // padding_mode='zeros': fold OOB validity into the weights
        wx0 *= (float)(x0 >= 0 && x0 < W);
        wx1 *= (float)(x0 >= -1 && x0 < W - 1);
        wy0 *= (float)(y0 >= 0 && y0 < W);
        wy1 *= (float)(y0 >= -1 && y0 < W - 1);

        int xc0 = min(max(x0, 0), W - 1);
        int xc1 = min(max(x0 + 1, 0), W - 1);
        int yc0 = min(max(y0, 0), W - 1);
        int yc1 = min(max(y0 + 1, 0), W - 1);

        const int base = b * NV + START;
        const int hh = h * HD;
        int r0 = (base + yc0 * W) << 8;
        int r1 = (base + yc1 * W) << 8;

        int4 ii;
        ii.x = r0 + (xc0 << 8) + hh;
        ii.y = r0 + (xc1 << 8) + hh;
        ii.z = r1 + (xc0 << 8) + hh;
        ii.w = r1 + (xc1 << 8) + hh;
        *(int4*)&meta[wloc][p][0] = ii;
        *(float4*)&meta[wloc][p][4] =
            make_float4(wp * wy0 * wx0, wp * wy0 * wx1, wp * wy1 * wx0, wp * wy1 * wx1);
    }
    __syncwarp();

    const int grp = lane >> 3;          // corner 0..3
    const int sub = lane & 7;           // channel quad 0..7
    const __nv_bfloat16* vb = g_vb;

    float a0 = 0.f, a1 = 0.f, a2 = 0.f, a3 = 0.f;
#pragma unroll
    for (int pt = 0; pt < 16; pt++) {
        int   idx = ((const int*)&meta[wloc][pt][0])[grp];
        float w   = meta[wloc][pt][4 + grp];
        uint2 raw = *(const uint2*)(vb + idx + sub * 4);
        __nv_bfloat162 p0 = *(__nv_bfloat162*)&raw.x;
        __nv_bfloat162 p1 = *(__nv_bfloat162*)&raw.y;
        float2 f0 = __bfloat1622float2(p0);
        float2 f1 = __bfloat1622float2(p1);
        a0 = fmaf(w, f0.x, a0);
        a1 = fmaf(w, f0.y, a1);
        a2 = fmaf(w, f1.x, a2);
        a3 = fmaf(w, f1.y, a3);
    }
#pragma unroll
    for (int o = 8; o <= 16; o <<= 1) {
        a0 += __shfl_xor_sync(0xffffffffu, a0, o);
        a1 += __shfl_xor_sync(0xffffffffu, a1, o);
        a2 += __shfl_xor_sync(0xffffffffu, a2, o);
        a3 += __shfl_xor_sync(0xffffffffu, a3, o);
    }
    if (grp == 0) {
        __nv_bfloat162 lo = __floats2bfloat162_rn(a0, a1);
        __nv_bfloat162 hi = __floats2bfloat162_rn(a2, a3);
        uint2 o; o.x = *(uint32_t*)&lo; o.y = *(uint32_t*)&hi;
        *(uint2*)&g_mid[bq * 256 + h * HD + sub * 4] = o;
    }
}

// ---------------------------------------------------------------------------
extern "C" void kernel_launch(void* const* d_in, const int* in_sizes, int n_in,
                              void* d_out, int out_size)
{
    const float* query  = (const float*)d_in[0];
    const float* value  = (const float*)d_in[1];
    const float* refp   = (const float*)d_in[2];
    const float* W_off  = (const float*)d_in[3];
    const float* b_off  = (const float*)d_in[4];
    const float* W_attn = (const float*)d_in[5];
    const float* b_attn = (const float*)d_in[6];
    const float* W_val  = (const float*)d_in[7];
    const float* b_val  = (const float*)d_in[8];
    const float* W_out  = (const float*)d_in[9];
    const float* b_out  = (const float*)d_in[10];
    float* out = (float*)d_out;

    float* pbrep;
    cudaGetSymbolAddress((void**)&pbrep, g_brep);

    cudaFuncSetAttribute(gemm_batched, cudaFuncAttributeMaxDynamicSharedMemorySize, GEMM_SMEM);
    cudaFuncSetAttribute(gemm_out,     cudaFuncAttributeMaxDynamicSharedMemorySize, GEMM_SMEM);

    // 0) replicated bias tiles + bf16 operand conversion
    fill_brep<<<64, 256>>>(b_val, b_off, b_attn, b_out);
    cvt_all<<<(S_TOT + 255) / 256, 256>>>(value, query, W_val, W_off, W_attn, W_out);

    // 1) all three input projections in one flat-grid launch (bf16 MMA)
    gemm_batched<<<T_ALL, 256, GEMM_SMEM>>>(pbrep);

    // 2) fused softmax + position precompute + grouped-corner gather
    sample_fused<<<(MQ * NH * 32 + 255) / 256, 256>>>(refp);

    // 3) output projection + bias + fp32 residual
    gemm_out<<<dim3(2, MQ_PAD / 128), 256, GEMM_SMEM>>>(pbrep, query, out);
}

// round 10
// speedup vs baseline: 3.9271x; 1.1554x over previous
#include <cuda_runtime.h>
#include <cuda_bf16.h>
#include <mma.h>
#include <math.h>
#include <stdint.h>

using namespace nvcuda;

#define BS 4
#define NQ 6000
#define NV 13294
#define EMB 256
#define NH 8
#define HD 32

#define MV (BS * NV)          // 53176
#define MQ (BS * NQ)          // 24000
#define MV_PAD 53248          // 416 * 128
#define MQ_PAD 24064          // 188 * 128

// tile counts for the batched input GEMM
#define T_VAL 832             // (MV_PAD/128) * 2
#define T_OFF 376             // (MQ_PAD/128) * 2
#define T_AW  188             // (MQ_PAD/128) * 1
#define T_ALL (T_VAL + T_OFF + T_AW)   // 1396

// Scratch (device globals: allocation-free per harness rules).
__device__ __nv_bfloat16 g_valb[(size_t)MV_PAD * EMB];  // value, bf16
__device__ __nv_bfloat16 g_qb  [(size_t)MQ_PAD * EMB];  // query, bf16
__device__ __nv_bfloat16 g_wv  [256 * 256];             // W_val  bf16
__device__ __nv_bfloat16 g_wof [256 * 256];             // W_off  bf16
__device__ __nv_bfloat16 g_wat [256 * 128];             // W_attn bf16
__device__ __nv_bfloat16 g_wo  [256 * 256];             // W_out  bf16
__device__ __nv_bfloat16 g_vb  [(size_t)NH * MV_PAD * HD];  // value proj, HEAD-MAJOR [h][pix][32]
__device__ float         g_off [(size_t)MQ_PAD * 256];  // sampling offsets
__device__ float         g_aw  [(size_t)MQ_PAD * 128];  // attn logits
__device__ __nv_bfloat16 g_mid [(size_t)MQ_PAD * 256];  // aggregated heads (bf16)
__device__ float         g_brep[4 * 16 * 256];          // 16-row-replicated bias tiles

// ---------------------------------------------------------------------------
// Fused conversion + bias-tile fill.
// float4 segments: value, query, W_val, W_off, W_attn, W_out (f32->bf16),
// then g_brep (f32 replicated bias rows; tile 2 = b_attn with N=128 wrap).
// ---------------------------------------------------------------------------
#define S_VAL (MV * 64)
#define S_QRY (MQ * 64)
#define S_W   16384
#define S_WA  8192
#define S_CVT (S_VAL + S_QRY + 3 * S_W + S_WA)
#define S_BRP 4096
#define S_TOT (S_CVT + S_BRP)

__global__ void cvt_all(const float* __restrict__ value, const float* __restrict__ query,
                        const float* __restrict__ Wv, const float* __restrict__ Wof,
                        const float* __restrict__ Wat, const float* __restrict__ Wo,
                        const float* __restrict__ b0, const float* __restrict__ b1,
                        const float* __restrict__ b2, const float* __restrict__ b3)
{
    int i = blockIdx.x * blockDim.x + threadIdx.x;
    if (i >= S_TOT) return;
    if (i >= S_CVT) {                 // bias tile segment (stays f32)
        int j = i - S_CVT;            // float4 index in [0, 4096)
        int t = j >> 10;              // tile 0..3
        int c4 = j & 63;              // float4 column within 256-wide row
        const float* b = (t == 0) ? b0 : (t == 1) ? b1 : (t == 2) ? b2 : b3;
        int col4 = (t == 2) ? (c4 & 31) : c4;
        ((float4*)g_brep)[j] = ((const float4*)b)[col4];
        return;
    }
    const float* src; __nv_bfloat16* dst;
    int j = i;
    if (j < S_VAL) { src = value; dst = g_valb; }
    else { j -= S_VAL;
        if (j < S_QRY) { src = query; dst = g_qb; }
        else { j -= S_QRY;
            if (j < S_W) { src = Wv; dst = g_wv; }
            else { j -= S_W;
                if (j < S_W) { src = Wof; dst = g_wof; }
                else { j -= S_W;
                    if (j < S_WA) { src = Wat; dst = g_wat; }
                    else { j -= S_WA; src = Wo; dst = g_wo; } } } } }
    float4 v = ((const float4*)src)[j];
    __nv_bfloat162 t0 = __floats2bfloat162_rn(v.x, v.y);
    __nv_bfloat162 t1 = __floats2bfloat162_rn(v.z, v.w);
    uint2 o; o.x = *(uint32_t*)&t0; o.y = *(uint32_t*)&t1;
    ((uint2*)dst)[j] = o;
}

// ---------------------------------------------------------------------------
// bf16 tensor-core GEMM core: wmma m16n16k16, cp.async double-buffered,
// BK=64, 128x128 block tile, 256 threads = 8 warps (4x2), warp tile 32x64.
// ---------------------------------------------------------------------------
#define AROW 72
#define BROW 136
#define A_ST (128 * AROW)
#define B_ST (64 * BROW)
#define GEMM_SMEM ((2 * A_ST + 2 * B_ST) * 2)   // 71680 bytes

__device__ __forceinline__ void cp16(void* dst_smem, const void* src, int src_bytes)
{
    uint32_t d = (uint32_t)__cvta_generic_to_shared(dst_smem);
    asm volatile("cp.async.cg.shared.global [%0], [%1], 16, %2;\n"
                 :: "r"(d), "l"(src), "r"(src_bytes));
}

struct GemmCore {
    __nv_bfloat16* As; __nv_bfloat16* Bsm;
    int tid, lane, wid, warp_m, warp_n, row0, col0;
    wmma::fragment<wmma::accumulator, 16, 16, 16, float> acc[2][4];

    __device__ __forceinline__ void init(char* sm, int r0, int c0, const float* brep)
    {
        As = (__nv_bfloat16*)sm; Bsm = As + 2 * A_ST;
        tid = threadIdx.x; lane = tid & 31; wid = tid >> 5;
        warp_m = wid >> 1; warp_n = wid & 1;
        row0 = r0; col0 = c0;
#pragma unroll
        for (int i = 0; i < 2; i++)
#pragma unroll
            for (int j = 0; j < 4; j++)
                wmma::load_matrix_sync(acc[i][j],
                    brep + col0 + warp_n * 64 + j * 16, 256, wmma::mem_row_major);
    }

    __device__ __forceinline__ void prefetch(const __nv_bfloat16* A, const __nv_bfloat16* B,
                                             int M, int N, int K, int k0, int st)
    {
        const int am = tid >> 3, ac = tid & 7;
        const int bk = tid >> 4, bc = tid & 15;
#pragma unroll
        for (int it = 0; it < 4; it++) {
            int m = am + it * 32;
            int r = row0 + m;
            cp16(&As[st * A_ST + m * AROW + ac * 8],
                 A + (size_t)r * K + k0 + ac * 8, (r < M) ? 16 : 0);
        }
#pragma unroll
        for (int it = 0; it < 4; it++) {
            int k = bk + it * 16;
            cp16(&Bsm[st * B_ST + k * BROW + bc * 8],
                 B + (size_t)(k0 + k) * N + col0 + bc * 8, 16);
        }
        asm volatile("cp.async.commit_group;\n");
    }

    __device__ __forceinline__ void mainloop(const __nv_bfloat16* A, const __nv_bfloat16* B,
                                             int M, int N, int K)
    {
        const int iters = K >> 6;
        prefetch(A, B, M, N, K, 0, 0);
        for (int i = 0; i < iters; i++) {
            if (i + 1 < iters) {
                prefetch(A, B, M, N, K, (i + 1) << 6, (i + 1) & 1);
                asm volatile("cp.async.wait_group 1;\n");
            } else {
                asm volatile("cp.async.wait_group 0;\n");
            }
            __syncthreads();
            const __nv_bfloat16* as = As + (i & 1) * A_ST;
            const __nv_bfloat16* bs = Bsm + (i & 1) * B_ST;
#pragma unroll
            for (int kk = 0; kk < 4; kk++) {
                wmma::fragment<wmma::matrix_a, 16, 16, 16, __nv_bfloat16, wmma::row_major> a[2];
                wmma::fragment<wmma::matrix_b, 16, 16, 16, __nv_bfloat16, wmma::row_major> b[4];
#pragma unroll
                for (int ii = 0; ii < 2; ii++)
                    wmma::load_matrix_sync(a[ii], as + (warp_m * 32 + ii * 16) * AROW + kk * 16, AROW);
#pragma unroll
                for (int j = 0; j < 4; j++)
                    wmma::load_matrix_sync(b[j], bs + (kk * 16) * BROW + warp_n * 64 + j * 16, BROW);
#pragma unroll
                for (int ii = 0; ii < 2; ii++)
#pragma unroll
                    for (int j = 0; j < 4; j++)
                        wmma::mma_sync(acc[ii][j], a[ii], b[j], acc[ii][j]);
            }
            __syncthreads();
        }
    }

    __device__ __forceinline__ void store_f32(float* C, const float* resid, int N, int Mstore)
    {
        if ((row0 + warp_m * 32) >= Mstore) return;
#pragma unroll
        for (int i = 0; i < 2; i++)
#pragma unroll
            for (int j = 0; j < 4; j++) {
                size_t off = (size_t)(row0 + warp_m * 32 + i * 16) * N + col0 + warp_n * 64 + j * 16;
                if (resid) {
                    wmma::fragment<wmma::accumulator, 16, 16, 16, float> r;
                    wmma::load_matrix_sync(r, resid + off, N, wmma::mem_row_major);
#pragma unroll
                    for (int t = 0; t < r.num_elements; t++)
                        acc[i][j].x[t] += r.x[t];
                }
                wmma::store_matrix_sync(C + off, acc[i][j], N, wmma::mem_row_major);
            }
    }

    // bf16 epilogue with HEAD-MAJOR scatter: column gcol -> plane h = gcol>>5,
    // element (gcol&31) within the 32-channel pixel record.
    __device__ __forceinline__ void store_bf16_hm(__nv_bfloat16* Cb, char* sm)
    {
        float* scratch = (float*)sm + wid * 256;
#pragma unroll
        for (int i = 0; i < 2; i++)
#pragma unroll
            for (int j = 0; j < 4; j++) {
                __syncwarp();
                wmma::store_matrix_sync(scratch, acc[i][j], 16, wmma::mem_row_major);
                __syncwarp();
                int r = lane >> 1, cb = (lane & 1) * 8;
                const float* sp = scratch + r * 16 + cb;
                float4 f0 = *(const float4*)sp;
                float4 f1 = *(const float4*)(sp + 4);
                uint4 o;
                __nv_bfloat162 t0 = __floats2bfloat162_rn(f0.x, f0.y);
                __nv_bfloat162 t1 = __floats2bfloat162_rn(f0.z, f0.w);
                __nv_bfloat162 t2 = __floats2bfloat162_rn(f1.x, f1.y);
                __nv_bfloat162 t3 = __floats2bfloat162_rn(f1.z, f1.w);
                o.x = *(uint32_t*)&t0; o.y = *(uint32_t*)&t1;
                o.z = *(uint32_t*)&t2; o.w = *(uint32_t*)&t3;
                int grow = row0 + warp_m * 32 + i * 16 + r;     // pixel row
                int gcol = col0 + warp_n * 64 + j * 16 + cb;    // h*32 + ch
                size_t off = (size_t)(gcol >> 5) * (MV_PAD * HD) + (size_t)grow * HD + (gcol & 31);
                *(uint4*)(Cb + off) = o;
            }
    }
};

// ---------------------------------------------------------------------------
// Batched input GEMM (bf16): one flat grid covering 3 independent problems
// ---------------------------------------------------------------------------
__global__ __launch_bounds__(256, 2)
void gemm_batched(const float* __restrict__ brep)
{
    extern __shared__ char smc[];
    int t = blockIdx.x;

    const __nv_bfloat16 *A, *B;
    const float* brp;
    int M, N, row_t, col_t, prob;
    if (t < T_VAL) {
        prob = 0; A = g_valb; B = g_wv; brp = brep;
        M = MV; N = 256; row_t = t >> 1; col_t = t & 1;
    } else if (t < T_VAL + T_OFF) {
        int u = t - T_VAL;
        prob = 1; A = g_qb; B = g_wof; brp = brep + 4096;
        M = MQ; N = 256; row_t = u >> 1; col_t = u & 1;
    } else {
        int u = t - T_VAL - T_OFF;
        prob = 2; A = g_qb; B = g_wat; brp = brep + 2 * 4096;
        M = MQ; N = 128; row_t = u; col_t = 0;
    }

    GemmCore g;
    g.init(smc, row_t * 128, col_t * 128, brp);
    g.mainloop(A, B, M, N, 256);

    if (prob == 0)       g.store_bf16_hm(g_vb, smc);
    else if (prob == 1)  g.store_f32(g_off, nullptr, 256, MQ_PAD);
    else                 g.store_f32(g_aw,  nullptr, 128, MQ_PAD);
}

// ---------------------------------------------------------------------------
// Output projection + bias + fp32 residual
// ---------------------------------------------------------------------------
__global__ __launch_bounds__(256, 2)
void gemm_out(const float* __restrict__ brep, const float* __restrict__ query,
              float* __restrict__ out)
{
    extern __shared__ char smc[];
    GemmCore g;
    g.init(smc, blockIdx.y * 128, blockIdx.x * 128, brep + 3 * 4096);
    g.mainloop(g_mid, g_wo, MQ, 256, 256);
    g.store_f32(out, query, 256, MQ);
}

// ---------------------------------------------------------------------------
// Fused sampling: TWO (b,q,h) units per warp (16 lanes each).
// Phase 1: lane = unit*16 + p. 16-lane softmax (xor 8,4,2,1); each lane emits
//   its point's 4 corners as interleaved {idx, w} int2 pairs (2 STS.128).
// Phase 2: lane = {unit(1b) | corner(2b) | chanquad(2b)}. Per point: one
//   LDS.64 (idx+w) + one LDG.128 (16B = 8 bf16 channels, head-major so the
//   two x-corners coalesce into one 128B line ~50% of the time) + 8 FMA.
//   Cross-corner shfl reduction (xor 4,8); corner-0 lanes store 8 ch bf16.
// ---------------------------------------------------------------------------
#define HSTRIDE (MV_PAD * HD)     // per-head plane stride in g_vb

__global__ __launch_bounds__(256)
void sample_fused(const float* __restrict__ refp)
{
    __shared__ int2 meta[16][66];   // [unit_loc][pt*4+corner], +2 pad vs bank overlap

    const int warp = (blockIdx.x * blockDim.x + threadIdx.x) >> 5;
    const int lane = threadIdx.x & 31;
    const int half = lane >> 4;
    const int unit = warp * 2 + half;         // < MQ*NH exactly (12000 CTAs)
    const int uloc = (threadIdx.x >> 5) * 2 + half;

    const int h  = unit & 7;
    const int bq = unit >> 3;
    const int b  = bq / NQ;

    // ---- Phase 1: softmax + corner metadata (all 32 lanes, p = lane&15) ----
    {
        const int p = lane & 15;
        const float* awp = g_aw + bq * 128 + h * 16;
        float a = awp[p];
        float m = a;
#pragma unroll
        for (int o = 8; o; o >>= 1) m = fmaxf(m, __shfl_xor_sync(0xffffffffu, m, o));
        float e = __expf(a - m);
        float s = e;
#pragma unroll
        for (int o = 8; o; o >>= 1) s += __shfl_xor_sync(0xffffffffu, s, o);
        const float wp = e / s;

        const int l = p >> 2;
        const int W = (0x0D193264 >> (l * 8)) & 0xFF;               // 100,50,25,13
        const long long spack = 0LL | (10000LL << 14) | (12500LL << 28) | (13125LL << 42);
        const int START = (int)((spack >> (14 * l)) & 0x3FFF);      // 0,10000,12500,13125

        const float* offp = g_off + bq * 256 + h * 32;
        float rx = refp[bq * 8 + 2 * l];
        float ry = refp[bq * 8 + 2 * l + 1];

        float x = fmaf(rx, (float)W, offp[2 * p]) - 0.5f;
        float y = fmaf(ry, (float)W, offp[2 * p + 1]) - 0.5f;
        float xf = floorf(x), yf = floorf(y);
        int   x0 = (int)xf,  y0 = (int)yf;
        float wx1 = x - xf, wy1 = y - yf;
        float wx0 = 1.f - wx1, wy0 = 1.f - wy1;

        // padding_mode='zeros': fold OOB validity into the weights
        wx0 *= (float)(x0 >= 0 && x0 < W);
        wx1 *= (float)(x0 >= -1 && x0 < W - 1);
        wy0 *= (float)(y0 >= 0 && y0 < W);
        wy1 *= (float)(y0 >= -1 && y0 < W - 1);

        int xc0 = min(max(x0, 0), W - 1);
        int xc1 = min(max(x0 + 1, 0), W - 1);
        int yc0 = min(max(y0, 0), W - 1);
        int yc1 = min(max(y0 + 1, 0), W - 1);

        const int hb   = h * HSTRIDE;                 // head plane
        const int base = b * NV + START;
        int r0 = hb + (base + yc0 * W) * HD;
        int r1 = hb + (base + yc1 * W) * HD;

        int2* mp = &meta[uloc][p * 4];
        *(int4*)(mp)     = make_int4(r0 + xc0 * HD, __float_as_int(wp * wy0 * wx0),
                                     r0 + xc1 * HD, __float_as_int(wp * wy0 * wx1));
        *(int4*)(mp + 2) = make_int4(r1 + xc0 * HD, __float_as_int(wp * wy1 * wx0),
                                     r1 + xc1 * HD, __float_as_int(wp * wy1 * wx1));
    }
    __syncwarp();

    // ---- Phase 2: gather ----
    const int corner = (lane >> 2) & 3;
    const int sub    = lane & 3;              // channel quad (8 ch = 16B)
    const __nv_bfloat16* vbp = g_vb + sub * 8;
    const int2* mrow = &meta[uloc][corner];

    float a0 = 0.f, a1 = 0.f, a2 = 0.f, a3 = 0.f, a4 = 0.f, a5 = 0.f, a6 = 0.f, a7 = 0.f;
#pragma unroll
    for (int pt = 0; pt < 16; pt++) {
        int2 md = mrow[pt * 4];
        float w = __int_as_float(md.y);
        uint4 raw = *(const uint4*)(vbp + md.x);
        float2 f0 = __bfloat1622float2(*(__nv_bfloat162*)&raw.x);
        float2 f1 = __bfloat1622float2(*(__nv_bfloat162*)&raw.y);
        float2 f2 = __bfloat1622float2(*(__nv_bfloat162*)&raw.z);
        float2 f3 = __bfloat1622float2(*(__nv_bfloat162*)&raw.w);
        a0 = fmaf(w, f0.x, a0); a1 = fmaf(w, f0.y, a1);
        a2 = fmaf(w, f1.x, a2); a3 = fmaf(w, f1.y, a3);
        a4 = fmaf(w, f2.x, a4); a5 = fmaf(w, f2.y, a5);
        a6 = fmaf(w, f3.x, a6); a7 = fmaf(w, f3.y, a7);
    }
    // reduce across the 4 corner lanes (xor 4, 8) within each 16-lane half
#pragma unroll
    for (int o = 4; o <= 8; o <<= 1) {
        a0 += __shfl_xor_sync(0xffffffffu, a0, o);
        a1 += __shfl_xor_sync(0xffffffffu, a1, o);
        a2 += __shfl_xor_sync(0xffffffffu, a2, o);
        a3 += __shfl_xor_sync(0xffffffffu, a3, o);
        a4 += __shfl_xor_sync(0xffffffffu, a4, o);
        a5 += __shfl_xor_sync(0xffffffffu, a5, o);
        a6 += __shfl_xor_sync(0xffffffffu, a6, o);
        a7 += __shfl_xor_sync(0xffffffffu, a7, o);
    }
    if (corner == 0) {
        __nv_bfloat162 t0 = __floats2bfloat162_rn(a0, a1);
        __nv_bfloat162 t1 = __floats2bfloat162_rn(a2, a3);
        __nv_bfloat162 t2 = __floats2bfloat162_rn(a4, a5);
        __nv_bfloat162 t3 = __floats2bfloat162_rn(a6, a7);
        uint4 o;
        o.x = *(uint32_t*)&t0; o.y = *(uint32_t*)&t1;
        o.z = *(uint32_t*)&t2; o.w = *(uint32_t*)&t3;
        *(uint4*)&g_mid[bq * 256 + h * HD + sub * 8] = o;
    }
}

// ---------------------------------------------------------------------------
extern "C" void kernel_launch(void* const* d_in, const int* in_sizes, int n_in,
                              void* d_out, int out_size)
{
    const float* query  = (const float*)d_in[0];
    const float* value  = (const float*)d_in[1];
    const float* refp   = (const float*)d_in[2];
    const float* W_off  = (const float*)d_in[3];
    const float* b_off  = (const float*)d_in[4];
    const float* W_attn = (const float*)d_in[5];
    const float* b_attn = (const float*)d_in[6];
    const float* W_val  = (const float*)d_in[7];
    const float* b_val  = (const float*)d_in[8];
    const float* W_out  = (const float*)d_in[9];
    const float* b_out  = (const float*)d_in[10];
    float* out = (float*)d_out;

    float* pbrep;
    cudaGetSymbolAddress((void**)&pbrep, g_brep);

    cudaFuncSetAttribute(gemm_batched, cudaFuncAttributeMaxDynamicSharedMemorySize, GEMM_SMEM);
    cudaFuncSetAttribute(gemm_out,     cudaFuncAttributeMaxDynamicSharedMemorySize, GEMM_SMEM);

    // 0) fused bf16 conversion + bias tile fill
    cvt_all<<<(S_TOT + 255) / 256, 256>>>(value, query, W_val, W_off, W_attn, W_out,
                                          b_val, b_off, b_attn, b_out);

    // 1) all three input projections in one flat-grid launch (bf16 MMA)
    gemm_batched<<<T_ALL, 256, GEMM_SMEM>>>(pbrep);

    // 2) fused sampler: 2 units/warp, head-major gather
    sample_fused<<<(MQ * NH) / 16, 256>>>(refp);

    // 3) output projection + bias + fp32 residual
    gemm_out<<<dim3(2, MQ_PAD / 128), 256, GEMM_SMEM>>>(pbrep, query, out);
}

// round 11
// speedup vs baseline: 3.9829x; 1.0142x over previous
#include <cuda_runtime.h>
#include <cuda_bf16.h>
#include <mma.h>
#include <math.h>
#include <stdint.h>

using namespace nvcuda;

#define BS 4
#define NQ 6000
#define NV 13294
#define EMB 256
#define NH 8
#define HD 32

#define MV (BS * NV)          // 53176
#define MQ (BS * NQ)          // 24000
#define MV_PAD 53248          // 416 * 128
#define MQ_PAD 24064          // 188 * 128

// tile counts for the batched input GEMM
#define T_VAL 832             // (MV_PAD/128) * 2
#define T_OFF 376             // (MQ_PAD/128) * 2
#define T_AW  188             // (MQ_PAD/128) * 1
#define T_ALL (T_VAL + T_OFF + T_AW)   // 1396

// Scratch (device globals: allocation-free per harness rules).
__device__ __nv_bfloat16 g_valb[(size_t)MV_PAD * EMB];  // value, bf16
__device__ __nv_bfloat16 g_qb  [(size_t)MQ_PAD * EMB];  // query, bf16
__device__ __nv_bfloat16 g_wv  [256 * 256];             // W_val  bf16
__device__ __nv_bfloat16 g_wof [256 * 256];             // W_off  bf16
__device__ __nv_bfloat16 g_wat [256 * 128];             // W_attn bf16
__device__ __nv_bfloat16 g_wo  [256 * 256];             // W_out  bf16
__device__ __nv_bfloat16 g_vb  [(size_t)NH * MV_PAD * HD];  // value proj, HEAD-MAJOR [h][pix][32]
__device__ float         g_off [(size_t)MQ_PAD * 256];  // sampling offsets
__device__ float         g_aw  [(size_t)MQ_PAD * 128];  // attn logits
__device__ __nv_bfloat16 g_mid [(size_t)MQ_PAD * 256];  // aggregated heads (bf16)
__device__ float         g_brep[4 * 16 * 256];          // 16-row-replicated bias tiles

// ---------------------------------------------------------------------------
// Fused conversion + bias-tile fill.
// ---------------------------------------------------------------------------
#define S_VAL (MV * 64)
#define S_QRY (MQ * 64)
#define S_W   16384
#define S_WA  8192
#define S_CVT (S_VAL + S_QRY + 3 * S_W + S_WA)
#define S_BRP 4096
#define S_TOT (S_CVT + S_BRP)

__global__ void cvt_all(const float* __restrict__ value, const float* __restrict__ query,
                        const float* __restrict__ Wv, const float* __restrict__ Wof,
                        const float* __restrict__ Wat, const float* __restrict__ Wo,
                        const float* __restrict__ b0, const float* __restrict__ b1,
                        const float* __restrict__ b2, const float* __restrict__ b3)
{
    int i = blockIdx.x * blockDim.x + threadIdx.x;
    if (i >= S_TOT) return;
    if (i >= S_CVT) {                 // bias tile segment (stays f32)
        int j = i - S_CVT;
        int t = j >> 10;
        int c4 = j & 63;
        const float* b = (t == 0) ? b0 : (t == 1) ? b1 : (t == 2) ? b2 : b3;
        int col4 = (t == 2) ? (c4 & 31) : c4;
        ((float4*)g_brep)[j] = ((const float4*)b)[col4];
        return;
    }
    const float* src; __nv_bfloat16* dst;
    int j = i;
    if (j < S_VAL) { src = value; dst = g_valb; }
    else { j -= S_VAL;
        if (j < S_QRY) { src = query; dst = g_qb; }
        else { j -= S_QRY;
            if (j < S_W) { src = Wv; dst = g_wv; }
            else { j -= S_W;
                if (j < S_W) { src = Wof; dst = g_wof; }
                else { j -= S_W;
                    if (j < S_WA) { src = Wat; dst = g_wat; }
                    else { j -= S_WA; src = Wo; dst = g_wo; } } } } }
    float4 v = ((const float4*)src)[j];
    __nv_bfloat162 t0 = __floats2bfloat162_rn(v.x, v.y);
    __nv_bfloat162 t1 = __floats2bfloat162_rn(v.z, v.w);
    uint2 o; o.x = *(uint32_t*)&t0; o.y = *(uint32_t*)&t1;
    ((uint2*)dst)[j] = o;
}

// ---------------------------------------------------------------------------
// bf16 tensor-core GEMM core: wmma m16n16k16.
// 4-stage cp.async pipeline (depth 3), BK=32, ONE __syncthreads per iter.
// 128x128 block tile, 256 threads = 8 warps (4x2), warp tile 32x64.
// ---------------------------------------------------------------------------
#define AROW 40                    // A smem row stride (bf16; 20-word rows -> conflict-free LDSM)
#define BROW 136                   // B smem row stride
#define A_ST (128 * AROW)          // 5120 bf16 per A stage
#define B_ST (32 * BROW)           // 4352 bf16 per B stage
#define NSTG 4
#define GEMM_SMEM (NSTG * (A_ST + B_ST) * 2)   // 75776 bytes

__device__ __forceinline__ void cp16(void* dst_smem, const void* src, int src_bytes)
{
    uint32_t d = (uint32_t)__cvta_generic_to_shared(dst_smem);
    asm volatile("cp.async.cg.shared.global [%0], [%1], 16, %2;\n"
                 :: "r"(d), "l"(src), "r"(src_bytes));
}

template<int N> __device__ __forceinline__ void cpwait()
{
    asm volatile("cp.async.wait_group %0;\n" :: "n"(N));
}

struct GemmCore {
    __nv_bfloat16* As; __nv_bfloat16* Bsm;
    int tid, lane, wid, warp_m, warp_n, row0, col0;
    wmma::fragment<wmma::accumulator, 16, 16, 16, float> acc[2][4];

    __device__ __forceinline__ void init(char* sm, int r0, int c0, const float* brep)
    {
        As = (__nv_bfloat16*)sm; Bsm = As + NSTG * A_ST;
        tid = threadIdx.x; lane = tid & 31; wid = tid >> 5;
        warp_m = wid >> 1; warp_n = wid & 1;
        row0 = r0; col0 = c0;
#pragma unroll
        for (int i = 0; i < 2; i++)
#pragma unroll
            for (int j = 0; j < 4; j++)
                wmma::load_matrix_sync(acc[i][j],
                    brep + col0 + warp_n * 64 + j * 16, 256, wmma::mem_row_major);
    }

    // One BK=32 stage: A tile 128x32, B tile 32x128 (one cp.async group)
    __device__ __forceinline__ void prefetch(const __nv_bfloat16* A, const __nv_bfloat16* B,
                                             int M, int N, int K, int k0, int st)
    {
        const int am = tid >> 2, ac = tid & 3;     // A: row 0..63 (x2), 16B chunk 0..3
        const int bk = tid >> 4, bc = tid & 15;    // B: k 0..15 (x2), 16B chunk 0..15
#pragma unroll
        for (int it = 0; it < 2; it++) {
            int m = am + it * 64;
            int r = row0 + m;
            cp16(&As[st * A_ST + m * AROW + ac * 8],
                 A + (size_t)r * K + k0 + ac * 8, (r < M) ? 16 : 0);
        }
#pragma unroll
        for (int it = 0; it < 2; it++) {
            int k = bk + it * 16;
            cp16(&Bsm[st * B_ST + k * BROW + bc * 8],
                 B + (size_t)(k0 + k) * N + col0 + bc * 8, 16);
        }
        asm volatile("cp.async.commit_group;\n");
    }

    __device__ __forceinline__ void compute_stage(int st)
    {
        const __nv_bfloat16* as = As + st * A_ST;
        const __nv_bfloat16* bs = Bsm + st * B_ST;
#pragma unroll
        for (int kk = 0; kk < 2; kk++) {
            wmma::fragment<wmma::matrix_a, 16, 16, 16, __nv_bfloat16, wmma::row_major> a[2];
            wmma::fragment<wmma::matrix_b, 16, 16, 16, __nv_bfloat16, wmma::row_major> b[4];
#pragma unroll
            for (int ii = 0; ii < 2; ii++)
                wmma::load_matrix_sync(a[ii], as + (warp_m * 32 + ii * 16) * AROW + kk * 16, AROW);
#pragma unroll
            for (int j = 0; j < 4; j++)
                wmma::load_matrix_sync(b[j], bs + (kk * 16) * BROW + warp_n * 64 + j * 16, BROW);
#pragma unroll
            for (int ii = 0; ii < 2; ii++)
#pragma unroll
                for (int j = 0; j < 4; j++)
                    wmma::mma_sync(acc[ii][j], a[ii], b[j], acc[ii][j]);
        }
    }

    // ITERS = K/32, compile-time. Depth-3 prefetch, single barrier per iter.
    // Overwrite hazard is safe: prefetch(i+3) targets buffer (i-1)&3, whose
    // readers all passed the top-of-iter-i barrier before the prefetch issues.
    template<int ITERS>
    __device__ __forceinline__ void mainloop(const __nv_bfloat16* A, const __nv_bfloat16* B,
                                             int M, int N, int K)
    {
        prefetch(A, B, M, N, K, 0,  0);
        prefetch(A, B, M, N, K, 32, 1);
        prefetch(A, B, M, N, K, 64, 2);
#pragma unroll
        for (int i = 0; i < ITERS; i++) {
            if (i < ITERS - 2)      cpwait<2>();
            else if (i == ITERS - 2) cpwait<1>();
            else                     cpwait<0>();
            __syncthreads();
            if (i + 3 < ITERS)
                prefetch(A, B, M, N, K, (i + 3) * 32, (i + 3) & 3);
            compute_stage(i & 3);
        }
    }

    __device__ __forceinline__ void store_f32(float* C, const float* resid, int N, int Mstore)
    {
        if ((row0 + warp_m * 32) >= Mstore) return;
#pragma unroll
        for (int i = 0; i < 2; i++)
#pragma unroll
            for (int j = 0; j < 4; j++) {
                size_t off = (size_t)(row0 + warp_m * 32 + i * 16) * N + col0 + warp_n * 64 + j * 16;
                if (resid) {
                    wmma::fragment<wmma::accumulator, 16, 16, 16, float> r;
                    wmma::load_matrix_sync(r, resid + off, N, wmma::mem_row_major);
#pragma unroll
                    for (int t = 0; t < r.num_elements; t++)
                        acc[i][j].x[t] += r.x[t];
                }
                wmma::store_matrix_sync(C + off, acc[i][j], N, wmma::mem_row_major);
            }
    }

    // bf16 epilogue with HEAD-MAJOR scatter. Per-warp scratch sits in the
    // A-stage-0 region, which no warp reads after the last barrier.
    __device__ __forceinline__ void store_bf16_hm(__nv_bfloat16* Cb, char* sm)
    {
        float* scratch = (float*)sm + wid * 256;
#pragma unroll
        for (int i = 0; i < 2; i++)
#pragma unroll
            for (int j = 0; j < 4; j++) {
                __syncwarp();
                wmma::store_matrix_sync(scratch, acc[i][j], 16, wmma::mem_row_major);
                __syncwarp();
                int r = lane >> 1, cb = (lane & 1) * 8;
                const float* sp = scratch + r * 16 + cb;
                float4 f0 = *(const float4*)sp;
                float4 f1 = *(const float4*)(sp + 4);
                uint4 o;
                __nv_bfloat162 t0 = __floats2bfloat162_rn(f0.x, f0.y);
                __nv_bfloat162 t1 = __floats2bfloat162_rn(f0.z, f0.w);
                __nv_bfloat162 t2 = __floats2bfloat162_rn(f1.x, f1.y);
                __nv_bfloat162 t3 = __floats2bfloat162_rn(f1.z, f1.w);
                o.x = *(uint32_t*)&t0; o.y = *(uint32_t*)&t1;
                o.z = *(uint32_t*)&t2; o.w = *(uint32_t*)&t3;
                int grow = row0 + warp_m * 32 + i * 16 + r;
                int gcol = col0 + warp_n * 64 + j * 16 + cb;
                size_t off = (size_t)(gcol >> 5) * (MV_PAD * HD) + (size_t)grow * HD + (gcol & 31);
                *(uint4*)(Cb + off) = o;
            }
    }
};

// ---------------------------------------------------------------------------
// Batched input GEMM (bf16): one flat grid covering 3 independent problems
// ---------------------------------------------------------------------------
__global__ __launch_bounds__(256, 2)
void gemm_batched(const float* __restrict__ brep)
{
    extern __shared__ char smc[];
    int t = blockIdx.x;

    const __nv_bfloat16 *A, *B;
    const float* brp;
    int M, N, row_t, col_t, prob;
    if (t < T_VAL) {
        prob = 0; A = g_valb; B = g_wv; brp = brep;
        M = MV; N = 256; row_t = t >> 1; col_t = t & 1;
    } else if (t < T_VAL + T_OFF) {
        int u = t - T_VAL;
        prob = 1; A = g_qb; B = g_wof; brp = brep + 4096;
        M = MQ; N = 256; row_t = u >> 1; col_t = u & 1;
    } else {
        int u = t - T_VAL - T_OFF;
        prob = 2; A = g_qb; B = g_wat; brp = brep + 2 * 4096;
        M = MQ; N = 128; row_t = u; col_t = 0;
    }

    GemmCore g;
    g.init(smc, row_t * 128, col_t * 128, brp);
    g.mainloop<8>(A, B, M, N, 256);

    if (prob == 0)       g.store_bf16_hm(g_vb, smc);
    else if (prob == 1)  g.store_f32(g_off, nullptr, 256, MQ_PAD);
    else                 g.store_f32(g_aw,  nullptr, 128, MQ_PAD);
}

// ---------------------------------------------------------------------------
// Output projection + bias + fp32 residual
// ---------------------------------------------------------------------------
__global__ __launch_bounds__(256, 2)
void gemm_out(const float* __restrict__ brep, const float* __restrict__ query,
              float* __restrict__ out)
{
    extern __shared__ char smc[];
    GemmCore g;
    g.init(smc, blockIdx.y * 128, blockIdx.x * 128, brep + 3 * 4096);
    g.mainloop<8>(g_mid, g_wo, MQ, 256, 256);
    g.store_f32(out, query, 256, MQ);
}

// ---------------------------------------------------------------------------
// Fused sampling: TWO (b,q,h) units per warp (16 lanes each). Unchanged.
// ---------------------------------------------------------------------------
#define HSTRIDE (MV_PAD * HD)     // per-head plane stride in g_vb

__global__ __launch_bounds__(256)
void sample_fused(const float* __restrict__ refp)
{
    __shared__ int2 meta[16][66];

    const int warp = (blockIdx.x * blockDim.x + threadIdx.x) >> 5;
    const int lane = threadIdx.x & 31;
    const int half = lane >> 4;
    const int unit = warp * 2 + half;
    const int uloc = (threadIdx.x >> 5) * 2 + half;

    const int h  = unit & 7;
    const int bq = unit >> 3;
    const int b  = bq / NQ;

    // ---- Phase 1: softmax + corner metadata (all 32 lanes, p = lane&15) ----
    {
        const int p = lane & 15;
        const float* awp = g_aw + bq * 128 + h * 16;
        float a = awp[p];
        float m = a;
#pragma unroll
        for (int o = 8; o; o >>= 1) m = fmaxf(m, __shfl_xor_sync(0xffffffffu, m, o));
        float e = __expf(a - m);
        float s = e;
#pragma unroll
        for (int o = 8; o; o >>= 1) s += __shfl_xor_sync(0xffffffffu, s, o);
        const float wp = e / s;

        const int l = p >> 2;
        const int W = (0x0D193264 >> (l * 8)) & 0xFF;               // 100,50,25,13
        const long long spack = 0LL | (10000LL << 14) | (12500LL << 28) | (13125LL << 42);
        const int START = (int)((spack >> (14 * l)) & 0x3FFF);      // 0,10000,12500,13125

        const float* offp = g_off + bq * 256 + h * 32;
        float rx = refp[bq * 8 + 2 * l];
        float ry = refp[bq * 8 + 2 * l + 1];

        float x = fmaf(rx, (float)W, offp[2 * p]) - 0.5f;
        float y = fmaf(ry, (float)W, offp[2 * p + 1]) - 0.5f;
        float xf = floorf(x), yf = floorf(y);
        int   x0 = (int)xf,  y0 = (int)yf;
        float wx1 = x - xf, wy1 = y - yf;
        float wx0 = 1.f - wx1, wy0 = 1.f - wy1;

        wx0 *= (float)(x0 >= 0 && x0 < W);
        wx1 *= (float)(x0 >= -1 && x0 < W - 1);
        wy0 *= (float)(y0 >= 0 && y0 < W);
        wy1 *= (float)(y0 >= -1 && y0 < W - 1);

        int xc0 = min(max(x0, 0), W - 1);
        int xc1 = min(max(x0 + 1, 0), W - 1);
        int yc0 = min(max(y0, 0), W - 1);
        int yc1 = min(max(y0 + 1, 0), W - 1);

        const int hb   = h * HSTRIDE;
        const int base = b * NV + START;
        int r0 = hb + (base + yc0 * W) * HD;
        int r1 = hb + (base + yc1 * W) * HD;

        int2* mp = &meta[uloc][p * 4];
        *(int4*)(mp)     = make_int4(r0 + xc0 * HD, __float_as_int(wp * wy0 * wx0),
                                     r0 + xc1 * HD, __float_as_int(wp * wy0 * wx1));
        *(int4*)(mp + 2) = make_int4(r1 + xc0 * HD, __float_as_int(wp * wy1 * wx0),
                                     r1 + xc1 * HD, __float_as_int(wp * wy1 * wx1));
    }
    __syncwarp();

    // ---- Phase 2: gather ----
    const int corner = (lane >> 2) & 3;
    const int sub    = lane & 3;
    const __nv_bfloat16* vbp = g_vb + sub * 8;
    const int2* mrow = &meta[uloc][corner];

    float a0 = 0.f, a1 = 0.f, a2 = 0.f, a3 = 0.f, a4 = 0.f, a5 = 0.f, a6 = 0.f, a7 = 0.f;
#pragma unroll
    for (int pt = 0; pt < 16; pt++) {
        int2 md = mrow[pt * 4];
        float w = __int_as_float(md.y);
        uint4 raw = *(const uint4*)(vbp + md.x);
        float2 f0 = __bfloat1622float2(*(__nv_bfloat162*)&raw.x);
        float2 f1 = __bfloat1622float2(*(__nv_bfloat162*)&raw.y);
        float2 f2 = __bfloat1622float2(*(__nv_bfloat162*)&raw.z);
        float2 f3 = __bfloat1622float2(*(__nv_bfloat162*)&raw.w);
        a0 = fmaf(w, f0.x, a0); a1 = fmaf(w, f0.y, a1);
        a2 = fmaf(w, f1.x, a2); a3 = fmaf(w, f1.y, a3);
        a4 = fmaf(w, f2.x, a4); a5 = fmaf(w, f2.y, a5);
        a6 = fmaf(w, f3.x, a6); a7 = fmaf(w, f3.y, a7);
    }
#pragma unroll
    for (int o = 4; o <= 8; o <<= 1) {
        a0 += __shfl_xor_sync(0xffffffffu, a0, o);
        a1 += __shfl_xor_sync(0xffffffffu, a1, o);
        a2 += __shfl_xor_sync(0xffffffffu, a2, o);
        a3 += __shfl_xor_sync(0xffffffffu, a3, o);
        a4 += __shfl_xor_sync(0xffffffffu, a4, o);
        a5 += __shfl_xor_sync(0xffffffffu, a5, o);
        a6 += __shfl_xor_sync(0xffffffffu, a6, o);
        a7 += __shfl_xor_sync(0xffffffffu, a7, o);
    }
    if (corner == 0) {
        __nv_bfloat162 t0 = __floats2bfloat162_rn(a0, a1);
        __nv_bfloat162 t1 = __floats2bfloat162_rn(a2, a3);
        __nv_bfloat162 t2 = __floats2bfloat162_rn(a4, a5);
        __nv_bfloat162 t3 = __floats2bfloat162_rn(a6, a7);
        uint4 o;
        o.x = *(uint32_t*)&t0; o.y = *(uint32_t*)&t1;
        o.z = *(uint32_t*)&t2; o.w = *(uint32_t*)&t3;
        *(uint4*)&g_mid[bq * 256 + h * HD + sub * 8] = o;
    }
}

// ---------------------------------------------------------------------------
extern "C" void kernel_launch(void* const* d_in, const int* in_sizes, int n_in,
                              void* d_out, int out_size)
{
    const float* query  = (const float*)d_in[0];
    const float* value  = (const float*)d_in[1];
    const float* refp   = (const float*)d_in[2];
    const float* W_off  = (const float*)d_in[3];
    const float* b_off  = (const float*)d_in[4];
    const float* W_attn = (const float*)d_in[5];
    const float* b_attn = (const float*)d_in[6];
    const float* W_val  = (const float*)d_in[7];
    const float* b_val  = (const float*)d_in[8];
    const float* W_out  = (const float*)d_in[9];
    const float* b_out  = (const float*)d_in[10];
    float* out = (float*)d_out;

    float* pbrep;
    cudaGetSymbolAddress((void**)&pbrep, g_brep);

    cudaFuncSetAttribute(gemm_batched, cudaFuncAttributeMaxDynamicSharedMemorySize, GEMM_SMEM);
    cudaFuncSetAttribute(gemm_out,     cudaFuncAttributeMaxDynamicSharedMemorySize, GEMM_SMEM);

    // 0) fused bf16 conversion + bias tile fill
    cvt_all<<<(S_TOT + 255) / 256, 256>>>(value, query, W_val, W_off, W_attn, W_out,
                                          b_val, b_off, b_attn, b_out);

    // 1) all three input projections in one flat-grid launch (bf16 MMA)
    gemm_batched<<<T_ALL, 256, GEMM_SMEM>>>(pbrep);

    // 2) fused sampler: 2 units/warp, head-major gather
    sample_fused<<<(MQ * NH) / 16, 256>>>(refp);

    // 3) output projection + bias + fp32 residual
    gemm_out<<<dim3(2, MQ_PAD / 128), 256, GEMM_SMEM>>>(pbrep, query, out);
}